// round 1
// baseline (speedup 1.0000x reference)
#include <cuda_runtime.h>

#define TOKENS 9216
#define EDIM 256
#define SRCDIM 1024
#define NCODES 16384

// ---------------- device scratch (no allocations allowed) ----------------
__device__ float g_z[TOKENS * EDIM];                 // encoder output  [9216,256]
__device__ float g_ct[EDIM * NCODES];                // 2*codebook^T    [256,16384]
__device__ float g_e2[NCODES];                       // ||e||^2 per code
__device__ unsigned long long g_minkey[TOKENS];      // packed (score|idx)
__device__ float g_losssum;

// order-preserving float -> uint map (total order, works for negatives)
__device__ __forceinline__ unsigned int fkey(float f) {
    unsigned int u = __float_as_uint(f);
    return (u & 0x80000000u) ? ~u : (u | 0x80000000u);
}

// ---------------- init ----------------
__global__ void init_kernel() {
    int i = blockIdx.x * blockDim.x + threadIdx.x;
    if (i < TOKENS) g_minkey[i] = ~0ull;
    if (i == 0) g_losssum = 0.0f;
}

// ---------------- codebook transpose (and fold the factor 2) ----------------
__global__ void transpose_scale_kernel(const float* __restrict__ cb) {
    __shared__ float t[32][33];
    int n0 = blockIdx.x * 32;
    int k0 = blockIdx.y * 32;
    int tx = threadIdx.x, ty = threadIdx.y;
#pragma unroll
    for (int r = 0; r < 32; r += 8)
        t[ty + r][tx] = cb[(size_t)(n0 + ty + r) * EDIM + k0 + tx];
    __syncthreads();
#pragma unroll
    for (int r = 0; r < 32; r += 8)
        g_ct[(size_t)(k0 + ty + r) * NCODES + n0 + tx] = 2.0f * t[tx][ty + r];
}

// ---------------- ||e||^2 ----------------
__global__ void e2_kernel(const float* __restrict__ cb) {
    int warp = (blockIdx.x * blockDim.x + threadIdx.x) >> 5;
    int lane = threadIdx.x & 31;
    if (warp >= NCODES) return;
    const float* row = cb + (size_t)warp * EDIM;
    float s = 0.0f;
    for (int k = lane; k < EDIM; k += 32) { float v = row[k]; s += v * v; }
#pragma unroll
    for (int o = 16; o; o >>= 1) s += __shfl_xor_sync(0xffffffffu, s, o);
    if (lane == 0) g_e2[warp] = s;
}

// ---------------- encoder GEMM: z = x @ enc_w + enc_b ----------------
// M=9216, N=256, K=1024. 128x128 tile, 8x8 per thread.
__global__ void __launch_bounds__(256) enc_gemm(const float* __restrict__ A,
                                                const float* __restrict__ B,
                                                const float* __restrict__ bias) {
    const int K = SRCDIM, N = EDIM;
    __shared__ float As[8][128];
    __shared__ float Bs[8][128];
    int tid = threadIdx.x;
    int tx = tid & 15, ty = tid >> 4;
    int m0 = blockIdx.y * 128, n0 = blockIdx.x * 128;
    int arow = tid >> 1, acol = (tid & 1) * 4;
    int brow = tid >> 5, bcol = (tid & 31) * 4;
    float acc[8][8];
#pragma unroll
    for (int i = 0; i < 8; i++)
#pragma unroll
        for (int j = 0; j < 8; j++) acc[i][j] = 0.0f;

    for (int k0 = 0; k0 < K; k0 += 8) {
        float4 av = *(const float4*)(A + (size_t)(m0 + arow) * K + k0 + acol);
        As[acol + 0][arow] = av.x; As[acol + 1][arow] = av.y;
        As[acol + 2][arow] = av.z; As[acol + 3][arow] = av.w;
        float4 bv = *(const float4*)(B + (size_t)(k0 + brow) * N + n0 + bcol);
        *(float4*)&Bs[brow][bcol] = bv;
        __syncthreads();
#pragma unroll
        for (int kk = 0; kk < 8; kk++) {
            float a[8], b[8];
            *(float4*)(a)     = *(const float4*)&As[kk][ty * 8];
            *(float4*)(a + 4) = *(const float4*)&As[kk][ty * 8 + 4];
            *(float4*)(b)     = *(const float4*)&Bs[kk][tx * 8];
            *(float4*)(b + 4) = *(const float4*)&Bs[kk][tx * 8 + 4];
#pragma unroll
            for (int i = 0; i < 8; i++)
#pragma unroll
                for (int j = 0; j < 8; j++) acc[i][j] += a[i] * b[j];
        }
        __syncthreads();
    }
#pragma unroll
    for (int i = 0; i < 8; i++) {
        int m = m0 + ty * 8 + i;
        float* crow = g_z + (size_t)m * N + n0 + tx * 8;
#pragma unroll
        for (int j = 0; j < 8; j++) crow[j] = acc[i][j] + bias[n0 + tx * 8 + j];
    }
}

// ---------------- score GEMM + fused argmin ----------------
// score[t][n] = e2[n] - 2*z[t].e[n]  (z2 omitted: constant per row, avoids
// cancellation at magnitude 256). M=9216, N=16384, K=256.
__global__ void __launch_bounds__(256) score_argmin() {
    const int K = EDIM, N = NCODES;
    __shared__ float As[8][128];
    __shared__ float Bs[8][128];
    __shared__ float e2s[128];
    int tid = threadIdx.x;
    int tx = tid & 15, ty = tid >> 4;
    int m0 = blockIdx.y * 128, n0 = blockIdx.x * 128;
    if (tid < 128) e2s[tid] = g_e2[n0 + tid];
    int arow = tid >> 1, acol = (tid & 1) * 4;
    int brow = tid >> 5, bcol = (tid & 31) * 4;
    float acc[8][8];
#pragma unroll
    for (int i = 0; i < 8; i++)
#pragma unroll
        for (int j = 0; j < 8; j++) acc[i][j] = 0.0f;

    for (int k0 = 0; k0 < K; k0 += 8) {
        float4 av = *(const float4*)(g_z + (size_t)(m0 + arow) * K + k0 + acol);
        As[acol + 0][arow] = av.x; As[acol + 1][arow] = av.y;
        As[acol + 2][arow] = av.z; As[acol + 3][arow] = av.w;
        float4 bv = *(const float4*)(g_ct + (size_t)(k0 + brow) * N + n0 + bcol);
        *(float4*)&Bs[brow][bcol] = bv;
        __syncthreads();
#pragma unroll
        for (int kk = 0; kk < 8; kk++) {
            float a[8], b[8];
            *(float4*)(a)     = *(const float4*)&As[kk][ty * 8];
            *(float4*)(a + 4) = *(const float4*)&As[kk][ty * 8 + 4];
            *(float4*)(b)     = *(const float4*)&Bs[kk][tx * 8];
            *(float4*)(b + 4) = *(const float4*)&Bs[kk][tx * 8 + 4];
#pragma unroll
            for (int i = 0; i < 8; i++)
#pragma unroll
                for (int j = 0; j < 8; j++) acc[i][j] += a[i] * b[j];
        }
        __syncthreads();
    }
    // argmin epilogue: per-thread min over 8 cols, shuffle-reduce over the 16
    // threads sharing each row group, one atomicMin(u64) per row.
#pragma unroll
    for (int i = 0; i < 8; i++) {
        float best = 0.0f; int bn = 0;
#pragma unroll
        for (int j = 0; j < 8; j++) {
            float s = e2s[tx * 8 + j] - acc[i][j];
            if (j == 0 || s < best) { best = s; bn = tx * 8 + j; }
        }
        unsigned long long key =
            ((unsigned long long)fkey(best) << 32) | (unsigned int)(n0 + bn);
#pragma unroll
        for (int o = 8; o; o >>= 1) {
            unsigned long long other = __shfl_xor_sync(0xffffffffu, key, o);
            if (other < key) key = other;
        }
        if (tx == 0) atomicMin(&g_minkey[m0 + ty * 8 + i], key);
    }
}

// ---------------- decoder GEMM: out = codebook[idx] @ dec_w + dec_b ----------------
// M=9216, N=1024, K=256; A rows gathered by index.
__global__ void __launch_bounds__(256) dec_gemm(const float* __restrict__ cb,
                                                const float* __restrict__ B,
                                                const float* __restrict__ bias,
                                                float* __restrict__ C) {
    const int K = EDIM, N = SRCDIM;
    __shared__ float As[8][128];
    __shared__ float Bs[8][128];
    __shared__ int idxs[128];
    int tid = threadIdx.x;
    int tx = tid & 15, ty = tid >> 4;
    int m0 = blockIdx.y * 128, n0 = blockIdx.x * 128;
    if (tid < 128) idxs[tid] = (int)(g_minkey[m0 + tid] & 0xffffffffu);
    __syncthreads();
    int arow = tid >> 1, acol = (tid & 1) * 4;
    int brow = tid >> 5, bcol = (tid & 31) * 4;
    float acc[8][8];
#pragma unroll
    for (int i = 0; i < 8; i++)
#pragma unroll
        for (int j = 0; j < 8; j++) acc[i][j] = 0.0f;

    int myrow = idxs[arow];
    for (int k0 = 0; k0 < K; k0 += 8) {
        float4 av = *(const float4*)(cb + (size_t)myrow * EDIM + k0 + acol);
        As[acol + 0][arow] = av.x; As[acol + 1][arow] = av.y;
        As[acol + 2][arow] = av.z; As[acol + 3][arow] = av.w;
        float4 bv = *(const float4*)(B + (size_t)(k0 + brow) * N + n0 + bcol);
        *(float4*)&Bs[brow][bcol] = bv;
        __syncthreads();
#pragma unroll
        for (int kk = 0; kk < 8; kk++) {
            float a[8], b[8];
            *(float4*)(a)     = *(const float4*)&As[kk][ty * 8];
            *(float4*)(a + 4) = *(const float4*)&As[kk][ty * 8 + 4];
            *(float4*)(b)     = *(const float4*)&Bs[kk][tx * 8];
            *(float4*)(b + 4) = *(const float4*)&Bs[kk][tx * 8 + 4];
#pragma unroll
            for (int i = 0; i < 8; i++)
#pragma unroll
                for (int j = 0; j < 8; j++) acc[i][j] += a[i] * b[j];
        }
        __syncthreads();
    }
#pragma unroll
    for (int i = 0; i < 8; i++) {
        int m = m0 + ty * 8 + i;
        float* crow = C + (size_t)m * N + n0 + tx * 8;
#pragma unroll
        for (int j = 0; j < 8; j++) crow[j] = acc[i][j] + bias[n0 + tx * 8 + j];
    }
}

// ---------------- loss = 1.25 * mean((z_q - z)^2) ----------------
__global__ void loss_kernel(const float* __restrict__ cb) {
    __shared__ float red[256];
    int tid = threadIdx.x;
    float part = 0.0f;
    const int total = TOKENS * EDIM;
    for (int i = blockIdx.x * blockDim.x + tid; i < total; i += gridDim.x * blockDim.x) {
        int t = i >> 8;
        int id = (int)(g_minkey[t] & 0xffffffffu);
        float d = cb[(size_t)id * EDIM + (i & 255)] - g_z[i];
        part += d * d;
    }
    red[tid] = part;
    __syncthreads();
    for (int s = 128; s; s >>= 1) {
        if (tid < s) red[tid] += red[tid + s];
        __syncthreads();
    }
    if (tid == 0) atomicAdd(&g_losssum, red[0]);
}

__global__ void finalize_kernel(float* __restrict__ out, int n) {
    out[n - 1] = 1.25f * g_losssum / (float)(TOKENS * EDIM);
}

// ---------------- launch ----------------
extern "C" void kernel_launch(void* const* d_in, const int* in_sizes, int n_in,
                              void* d_out, int out_size) {
    const float* x     = (const float*)d_in[0];
    const float* enc_w = (const float*)d_in[1];
    const float* enc_b = (const float*)d_in[2];
    const float* cb    = (const float*)d_in[3];
    const float* dec_w = (const float*)d_in[4];
    const float* dec_b = (const float*)d_in[5];
    float* out = (float*)d_out;

    init_kernel<<<(TOKENS + 255) / 256, 256>>>();
    transpose_scale_kernel<<<dim3(NCODES / 32, EDIM / 32), dim3(32, 8)>>>(cb);
    e2_kernel<<<(NCODES * 32) / 256, 256>>>(cb);
    enc_gemm<<<dim3(EDIM / 128, TOKENS / 128), 256>>>(x, enc_w, enc_b);
    score_argmin<<<dim3(NCODES / 128, TOKENS / 128), 256>>>();
    dec_gemm<<<dim3(SRCDIM / 128, TOKENS / 128), 256>>>(cb, dec_w, dec_b, out);
    loss_kernel<<<72, 256>>>(cb);
    finalize_kernel<<<1, 1>>>(out, out_size);
}

// round 3
// speedup vs baseline: 2.2918x; 2.2918x over previous
#include <cuda_runtime.h>
#include <cuda_bf16.h>
#include <cstdint>

#define TOKENS 9216
#define EDIM 256
#define SRCDIM 1024
#define NCODES 16384

// ---------------- device scratch ----------------
__device__ float g_z[TOKENS * EDIM];
__device__ __nv_bfloat16 g_zhi[TOKENS * EDIM];
__device__ __nv_bfloat16 g_zlo[TOKENS * EDIM];
__device__ __nv_bfloat16 g_ehi[NCODES * EDIM];
__device__ __nv_bfloat16 g_elo[NCODES * EDIM];
__device__ __nv_bfloat16 g_dwt[SRCDIM * EDIM];   // dec_w transposed [n][k] bf16
__device__ float g_e2[NCODES];
__device__ unsigned long long g_minkey[TOKENS];
__device__ float g_losssum;

// ---------------- portable PTX helpers (sm_80-era only!) ----------------
__device__ __forceinline__ uint32_t smem_u32(const void* p) {
    uint32_t a;
    asm("{ .reg .u64 t; cvta.to.shared.u64 t, %1; cvt.u32.u64 %0, t; }" : "=r"(a) : "l"(p));
    return a;
}
__device__ __forceinline__ void cp_async16(uint32_t dst, const void* src) {
    asm volatile("cp.async.cg.shared.global [%0], [%1], 16;" :: "r"(dst), "l"(src) : "memory");
}
__device__ __forceinline__ void cp_commit() { asm volatile("cp.async.commit_group;" ::: "memory"); }
__device__ __forceinline__ void cp_wait0() { asm volatile("cp.async.wait_group 0;" ::: "memory"); }
__device__ __forceinline__ void cp_wait1() { asm volatile("cp.async.wait_group 1;" ::: "memory"); }

__device__ __forceinline__ void ldsm_x4(uint32_t& r0, uint32_t& r1, uint32_t& r2, uint32_t& r3,
                                        uint32_t addr) {
    asm volatile("ldmatrix.sync.aligned.m8n8.x4.shared.b16 {%0,%1,%2,%3}, [%4];"
                 : "=r"(r0), "=r"(r1), "=r"(r2), "=r"(r3) : "r"(addr));
}
__device__ __forceinline__ void mma16816(float* c, const uint32_t* a, const uint32_t* b) {
    asm volatile("mma.sync.aligned.m16n8k16.row.col.f32.bf16.bf16.f32 "
                 "{%0,%1,%2,%3}, {%4,%5,%6,%7}, {%8,%9}, {%0,%1,%2,%3};"
                 : "+f"(c[0]), "+f"(c[1]), "+f"(c[2]), "+f"(c[3])
                 : "r"(a[0]), "r"(a[1]), "r"(a[2]), "r"(a[3]), "r"(b[0]), "r"(b[1]));
}

__device__ __forceinline__ unsigned int fkey(float f) {
    unsigned int u = __float_as_uint(f);
    return (u & 0x80000000u) ? ~u : (u | 0x80000000u);
}

// ---------------- init ----------------
__global__ void init_kernel() {
    int i = blockIdx.x * blockDim.x + threadIdx.x;
    if (i < TOKENS) g_minkey[i] = ~0ull;
    if (i == 0) g_losssum = 0.0f;
}

// ---------------- codebook prep: bf16 split + ||e||^2 ----------------
__global__ void prep_cb(const float* __restrict__ cb) {
    int warp = (blockIdx.x * blockDim.x + threadIdx.x) >> 5;
    int lane = threadIdx.x & 31;
    if (warp >= NCODES) return;
    size_t base = (size_t)warp * EDIM;
    float s = 0.0f;
#pragma unroll
    for (int i = 0; i < 8; i++) {
        int k = lane * 8 + i;
        float v = cb[base + k];
        __nv_bfloat16 h = __float2bfloat16(v);
        __nv_bfloat16 l = __float2bfloat16(v - __bfloat162float(h));
        g_ehi[base + k] = h;
        g_elo[base + k] = l;
        s += v * v;
    }
#pragma unroll
    for (int o = 16; o; o >>= 1) s += __shfl_xor_sync(0xffffffffu, s, o);
    if (lane == 0) g_e2[warp] = s;
}

// ---------------- dec_w transpose to [n][k] bf16 ----------------
__global__ void prep_dwt(const float* __restrict__ dw) {
    __shared__ float t[32][33];
    int k0 = blockIdx.y * 32, n0 = blockIdx.x * 32;
    int tx = threadIdx.x, ty = threadIdx.y;
#pragma unroll
    for (int r = 0; r < 32; r += 8)
        t[ty + r][tx] = dw[(size_t)(k0 + ty + r) * SRCDIM + n0 + tx];
    __syncthreads();
#pragma unroll
    for (int r = 0; r < 32; r += 8)
        g_dwt[(size_t)(n0 + ty + r) * EDIM + k0 + tx] = __float2bfloat16(t[tx][ty + r]);
}

// ---------------- encoder GEMM (fp32): z = x @ enc_w + enc_b, + bf16 split ----------------
__global__ void __launch_bounds__(256) enc_gemm(const float* __restrict__ A,
                                                const float* __restrict__ B,
                                                const float* __restrict__ bias) {
    const int K = SRCDIM, N = EDIM;
    __shared__ float As[8][128];
    __shared__ float Bs[8][128];
    int tid = threadIdx.x;
    int tx = tid & 15, ty = tid >> 4;
    int m0 = blockIdx.y * 128, n0 = blockIdx.x * 128;
    int arow = tid >> 1, acol = (tid & 1) * 4;
    int brow = tid >> 5, bcol = (tid & 31) * 4;
    float acc[8][8];
#pragma unroll
    for (int i = 0; i < 8; i++)
#pragma unroll
        for (int j = 0; j < 8; j++) acc[i][j] = 0.0f;

    for (int k0 = 0; k0 < K; k0 += 8) {
        float4 av = *(const float4*)(A + (size_t)(m0 + arow) * K + k0 + acol);
        As[acol + 0][arow] = av.x; As[acol + 1][arow] = av.y;
        As[acol + 2][arow] = av.z; As[acol + 3][arow] = av.w;
        float4 bv = *(const float4*)(B + (size_t)(k0 + brow) * N + n0 + bcol);
        *(float4*)&Bs[brow][bcol] = bv;
        __syncthreads();
#pragma unroll
        for (int kk = 0; kk < 8; kk++) {
            float a[8], b[8];
            *(float4*)(a)     = *(const float4*)&As[kk][ty * 8];
            *(float4*)(a + 4) = *(const float4*)&As[kk][ty * 8 + 4];
            *(float4*)(b)     = *(const float4*)&Bs[kk][tx * 8];
            *(float4*)(b + 4) = *(const float4*)&Bs[kk][tx * 8 + 4];
#pragma unroll
            for (int i = 0; i < 8; i++)
#pragma unroll
                for (int j = 0; j < 8; j++) acc[i][j] += a[i] * b[j];
        }
        __syncthreads();
    }
#pragma unroll
    for (int i = 0; i < 8; i++) {
        int m = m0 + ty * 8 + i;
        size_t rb = (size_t)m * N + n0 + tx * 8;
#pragma unroll
        for (int j = 0; j < 8; j++) {
            float v = acc[i][j] + bias[n0 + tx * 8 + j];
            g_z[rb + j] = v;
            __nv_bfloat16 h = __float2bfloat16(v);
            g_zhi[rb + j] = h;
            g_zlo[rb + j] = __float2bfloat16(v - __bfloat162float(h));
        }
    }
}

// ==================== score kernel: mma.sync bf16, fused argmin ====================
// SMEM layout (dynamic):
//   [0, 64K)      A zhi: 128 rows x 256 k, row 512B, 16B-chunk XOR swizzle per 128B block
//   [64K, 128K)   A zlo
//   [128K,160K)   B stages: 2 x 16KB ([128 n][64 k], row 128B, swizzled)
//   [160K, +512)  e2 tile
//   [.., +1K)     per-row minkey (u64[128])
#define SCB_OFF  131072
#define SCE2_OFF 163840
#define SCMK_OFF 164352
#define SC_SMEM  165376

// load one B stage: [128 rows][64 k] bf16 from gsrc (row stride 256 elems)
__device__ __forceinline__ void load_b_stage(uint32_t sdst, const __nv_bfloat16* gsrc, int tid) {
#pragma unroll
    for (int i = 0; i < 4; i++) {
        int q = tid + 256 * i;              // 1024 16B chunks
        int r = q >> 3, c = q & 7;
        uint32_t dst = sdst + r * 128 + ((c ^ (r & 7)) << 4);
        cp_async16(dst, gsrc + (size_t)r * 256 + c * 8);
    }
}

__global__ void __launch_bounds__(256, 1) score_kernel() {
    extern __shared__ char sm[];
    uint32_t sb = smem_u32(sm);
    int tid = threadIdx.x;
    int lane = tid & 31, wid = tid >> 5;
    int warp_m = wid & 1, warp_n = wid >> 1;
    int m0 = blockIdx.y * 128;

    unsigned long long* mk = (unsigned long long*)(sm + SCMK_OFF);
    float* e2s = (float*)(sm + SCE2_OFF);
    if (tid < 128) mk[tid] = ~0ull;

    // ---- persistent A load (zhi + zlo) ----
    {
        const __nv_bfloat16* zh = g_zhi + (size_t)m0 * 256;
        const __nv_bfloat16* zl = g_zlo + (size_t)m0 * 256;
#pragma unroll
        for (int i = 0; i < 16; i++) {
            int q = tid + 256 * i;          // 4096 chunks
            int r = q >> 5, c = q & 31;
            uint32_t dst = sb + r * 512 + (c >> 3) * 128 + (((c & 7) ^ (r & 7)) << 4);
            cp_async16(dst, zh + (size_t)r * 256 + c * 8);
            cp_async16(dst + 65536, zl + (size_t)r * 256 + c * 8);
        }
        cp_commit();
        cp_wait0();
    }
    __syncthreads();

    float acc[4][4][4];
#pragma unroll
    for (int i = 0; i < 4; i++)
#pragma unroll
        for (int j = 0; j < 4; j++)
#pragma unroll
            for (int q = 0; q < 4; q++) acc[i][j][q] = 0.0f;

    for (int t = 0; t < 64; t++) {
        int n0 = (blockIdx.x * 64 + t) * 128;
        if (tid < 128) e2s[tid] = g_e2[n0 + tid];

        // prefetch stage 0 (B = ehi chunk 0)
        load_b_stage(sb + SCB_OFF, g_ehi + (size_t)n0 * 256, tid);
        cp_commit();

        for (int st = 0; st < 8; st++) {
            if (st < 7) {
                int sn = st + 1;
                const __nv_bfloat16* bp = (sn < 4 ? g_ehi : g_elo) + (size_t)n0 * 256 + (sn & 3) * 64;
                load_b_stage(sb + SCB_OFF + (sn & 1) * 16384, bp, tid);
                cp_commit();
                cp_wait1();
            } else {
                cp_wait0();
            }
            __syncthreads();

            uint32_t bbase = sb + SCB_OFF + (st & 1) * 16384;
            int kc = (st & 3) * 64;
            int npass = (st < 4) ? 2 : 1;
#pragma unroll
            for (int kk = 0; kk < 4; kk++) {
                uint32_t b[2][4];
#pragma unroll
                for (int jp = 0; jp < 2; jp++) {
                    int n = warp_n * 32 + jp * 16 + (lane & 7) + ((lane >> 4) << 3);
                    int ch = kk * 2 + ((lane >> 3) & 1);
                    uint32_t ad = bbase + n * 128 + ((ch ^ (n & 7)) << 4);
                    ldsm_x4(b[jp][0], b[jp][1], b[jp][2], b[jp][3], ad);
                }
                for (int p = 0; p < npass; p++) {
                    uint32_t abase = sb + (p == 1 ? 65536u : 0u);
#pragma unroll
                    for (int i = 0; i < 4; i++) {
                        int r = warp_m * 64 + i * 16 + (lane & 15);
                        int k = kc + kk * 16 + ((lane >> 4) << 3);
                        uint32_t ad = abase + r * 512 + (k >> 6) * 128 +
                                      ((((k >> 3) & 7) ^ (r & 7)) << 4);
                        uint32_t a[4];
                        ldsm_x4(a[0], a[1], a[2], a[3], ad);
#pragma unroll
                        for (int j = 0; j < 4; j++)
                            mma16816(acc[i][j], a, &b[j >> 1][(j & 1) * 2]);
                    }
                }
            }
            __syncthreads();
        }

        // ---- epilogue: score + argmin, reset acc ----
        float e2r[8];
#pragma unroll
        for (int j = 0; j < 4; j++) {
            int nl = warp_n * 32 + j * 8 + (lane & 3) * 2;
            e2r[j * 2] = e2s[nl];
            e2r[j * 2 + 1] = e2s[nl + 1];
        }
#pragma unroll
        for (int i = 0; i < 4; i++) {
#pragma unroll
            for (int half = 0; half < 2; half++) {
                float best = __int_as_float(0x7f800000);
                int bn = 0;
#pragma unroll
                for (int j = 0; j < 4; j++) {
#pragma unroll
                    for (int jj = 0; jj < 2; jj++) {
                        float s = fmaf(-2.0f, acc[i][j][half * 2 + jj], e2r[j * 2 + jj]);
                        acc[i][j][half * 2 + jj] = 0.0f;
                        int nl = warp_n * 32 + j * 8 + (lane & 3) * 2 + jj;
                        if (s < best) { best = s; bn = nl; }
                    }
                }
                unsigned long long key =
                    ((unsigned long long)fkey(best) << 32) | (unsigned int)(n0 + bn);
                unsigned long long o = __shfl_xor_sync(0xffffffffu, key, 1);
                if (o < key) key = o;
                o = __shfl_xor_sync(0xffffffffu, key, 2);
                if (o < key) key = o;
                if ((lane & 3) == 0)
                    atomicMin(&mk[warp_m * 64 + i * 16 + (lane >> 2) + half * 8], key);
            }
        }
        __syncthreads();
    }
    if (tid < 128) atomicMin(&g_minkey[m0 + tid], mk[tid]);
}

// ==================== decoder kernel: out = ehi[idx] @ dwt^T + dec_b ====================
// SMEM: A gathered [0,64K), B stages [64K,96K), idx [96K,+512)
#define DCB_OFF  65536
#define DCI_OFF  98304
#define DC_SMEM  98816

__global__ void __launch_bounds__(256, 2) dec_kernel(const float* __restrict__ bias,
                                                     float* __restrict__ C) {
    extern __shared__ char sm[];
    uint32_t sb = smem_u32(sm);
    int tid = threadIdx.x;
    int lane = tid & 31, wid = tid >> 5;
    int warp_m = wid & 1, warp_n = wid >> 1;
    int m0 = blockIdx.y * 128, n0 = blockIdx.x * 128;

    int* idxs = (int*)(sm + DCI_OFF);
    if (tid < 128) idxs[tid] = (int)(g_minkey[m0 + tid] & 0xffffffffu);
    __syncthreads();

    // gather A rows (ehi[idx], 128 x 256 bf16, swizzled, row 512B)
#pragma unroll
    for (int i = 0; i < 16; i++) {
        int q = tid + 256 * i;
        int r = q >> 5, c = q & 31;
        uint32_t dst = sb + r * 512 + (c >> 3) * 128 + (((c & 7) ^ (r & 7)) << 4);
        cp_async16(dst, g_ehi + (size_t)idxs[r] * 256 + c * 8);
    }
    cp_commit();
    // prefetch B stage 0
    load_b_stage(sb + DCB_OFF, g_dwt + (size_t)n0 * 256, tid);
    cp_commit();

    float acc[4][4][4];
#pragma unroll
    for (int i = 0; i < 4; i++)
#pragma unroll
        for (int j = 0; j < 4; j++)
#pragma unroll
            for (int q = 0; q < 4; q++) acc[i][j][q] = 0.0f;

    for (int st = 0; st < 4; st++) {
        if (st < 3) {
            load_b_stage(sb + DCB_OFF + ((st + 1) & 1) * 16384,
                         g_dwt + (size_t)n0 * 256 + (st + 1) * 64, tid);
            cp_commit();
            cp_wait1();
        } else {
            cp_wait0();
        }
        __syncthreads();

        uint32_t bbase = sb + DCB_OFF + (st & 1) * 16384;
        int kc = st * 64;
#pragma unroll
        for (int kk = 0; kk < 4; kk++) {
            uint32_t b[2][4];
#pragma unroll
            for (int jp = 0; jp < 2; jp++) {
                int n = warp_n * 32 + jp * 16 + (lane & 7) + ((lane >> 4) << 3);
                int ch = kk * 2 + ((lane >> 3) & 1);
                uint32_t ad = bbase + n * 128 + ((ch ^ (n & 7)) << 4);
                ldsm_x4(b[jp][0], b[jp][1], b[jp][2], b[jp][3], ad);
            }
#pragma unroll
            for (int i = 0; i < 4; i++) {
                int r = warp_m * 64 + i * 16 + (lane & 15);
                int k = kc + kk * 16 + ((lane >> 4) << 3);
                uint32_t ad = sb + r * 512 + (k >> 6) * 128 +
                              ((((k >> 3) & 7) ^ (r & 7)) << 4);
                uint32_t a[4];
                ldsm_x4(a[0], a[1], a[2], a[3], ad);
#pragma unroll
                for (int j = 0; j < 4; j++)
                    mma16816(acc[i][j], a, &b[j >> 1][(j & 1) * 2]);
            }
        }
        __syncthreads();
    }

    // epilogue: + bias, store fp32
#pragma unroll
    for (int j = 0; j < 4; j++) {
        int n = n0 + warp_n * 32 + j * 8 + (lane & 3) * 2;
        float b0 = bias[n], b1 = bias[n + 1];
#pragma unroll
        for (int i = 0; i < 4; i++) {
            int row = m0 + warp_m * 64 + i * 16 + (lane >> 2);
            float2 v0 = make_float2(acc[i][j][0] + b0, acc[i][j][1] + b1);
            float2 v1 = make_float2(acc[i][j][2] + b0, acc[i][j][3] + b1);
            *(float2*)(C + (size_t)row * SRCDIM + n) = v0;
            *(float2*)(C + (size_t)(row + 8) * SRCDIM + n) = v1;
        }
    }
}

// ---------------- loss = 1.25 * mean((z_q - z)^2) ----------------
__global__ void loss_kernel(const float* __restrict__ cb) {
    __shared__ float red[256];
    int tid = threadIdx.x;
    float part = 0.0f;
    const int total = TOKENS * EDIM;
    for (int i = blockIdx.x * blockDim.x + tid; i < total; i += gridDim.x * blockDim.x) {
        int t = i >> 8;
        int id = (int)(g_minkey[t] & 0xffffffffu);
        float d = cb[(size_t)id * EDIM + (i & 255)] - g_z[i];
        part += d * d;
    }
    red[tid] = part;
    __syncthreads();
    for (int s = 128; s; s >>= 1) {
        if (tid < s) red[tid] += red[tid + s];
        __syncthreads();
    }
    if (tid == 0) atomicAdd(&g_losssum, red[0]);
}

__global__ void finalize_kernel(float* __restrict__ out, int n) {
    out[n - 1] = 1.25f * g_losssum / (float)(TOKENS * EDIM);
}

// ---------------- launch ----------------
extern "C" void kernel_launch(void* const* d_in, const int* in_sizes, int n_in,
                              void* d_out, int out_size) {
    const float* x     = (const float*)d_in[0];
    const float* enc_w = (const float*)d_in[1];
    const float* enc_b = (const float*)d_in[2];
    const float* cb    = (const float*)d_in[3];
    const float* dec_w = (const float*)d_in[4];
    const float* dec_b = (const float*)d_in[5];
    float* out = (float*)d_out;

    static bool attr_done = false;
    if (!attr_done) {
        cudaFuncSetAttribute(score_kernel, cudaFuncAttributeMaxDynamicSharedMemorySize, SC_SMEM);
        cudaFuncSetAttribute(dec_kernel, cudaFuncAttributeMaxDynamicSharedMemorySize, DC_SMEM);
        attr_done = true;
    }

    init_kernel<<<(TOKENS + 255) / 256, 256>>>();
    prep_cb<<<(NCODES * 32) / 256, 256>>>(cb);
    prep_dwt<<<dim3(SRCDIM / 32, EDIM / 32), dim3(32, 8)>>>(dec_w);
    enc_gemm<<<dim3(EDIM / 128, TOKENS / 128), 256>>>(x, enc_w, enc_b);
    score_kernel<<<dim3(2, TOKENS / 128), 256, SC_SMEM>>>();
    dec_kernel<<<dim3(SRCDIM / 128, TOKENS / 128), 256, DC_SMEM>>>(dec_b, out);
    loss_kernel<<<296, 256>>>(cb);
    finalize_kernel<<<1, 1>>>(out, out_size);
}

// round 4
// speedup vs baseline: 3.9554x; 1.7259x over previous
#include <cuda_runtime.h>
#include <cuda_bf16.h>
#include <cstdint>

#define TOKENS 9216
#define EDIM 256
#define SRCDIM 1024
#define NCODES 16384
#define CAP 128
#define TAU 3e-5f

// ---------------- device scratch ----------------
__device__ float g_z[TOKENS * EDIM];
__device__ __nv_bfloat16 g_zhi[TOKENS * EDIM];
__device__ __nv_bfloat16 g_ehi[NCODES * EDIM];
__device__ __nv_bfloat16 g_xhi[TOKENS * SRCDIM];
__device__ __nv_bfloat16 g_xlo[TOKENS * SRCDIM];
__device__ __nv_bfloat16 g_ewhi[EDIM * SRCDIM];   // enc_w^T hi [n][k]
__device__ __nv_bfloat16 g_ewlo[EDIM * SRCDIM];   // enc_w^T lo
__device__ __nv_bfloat16 g_dwt[SRCDIM * EDIM];    // dec_w^T bf16 [n][k]
__device__ float g_e2[NCODES];
__device__ unsigned long long g_minkey[TOKENS];
__device__ int g_cndcnt[TOKENS];
__device__ unsigned int g_cand[TOKENS * CAP];
__device__ float g_losssum;

// ---------------- portable PTX helpers ----------------
__device__ __forceinline__ uint32_t smem_u32(const void* p) {
    uint32_t a;
    asm("{ .reg .u64 t; cvta.to.shared.u64 t, %1; cvt.u32.u64 %0, t; }" : "=r"(a) : "l"(p));
    return a;
}
__device__ __forceinline__ void cp_async16(uint32_t dst, const void* src) {
    asm volatile("cp.async.cg.shared.global [%0], [%1], 16;" :: "r"(dst), "l"(src) : "memory");
}
__device__ __forceinline__ void cp_commit() { asm volatile("cp.async.commit_group;" ::: "memory"); }
__device__ __forceinline__ void cp_wait0() { asm volatile("cp.async.wait_group 0;" ::: "memory"); }
__device__ __forceinline__ void cp_wait1() { asm volatile("cp.async.wait_group 1;" ::: "memory"); }

__device__ __forceinline__ void ldsm_x4(uint32_t& r0, uint32_t& r1, uint32_t& r2, uint32_t& r3,
                                        uint32_t addr) {
    asm volatile("ldmatrix.sync.aligned.m8n8.x4.shared.b16 {%0,%1,%2,%3}, [%4];"
                 : "=r"(r0), "=r"(r1), "=r"(r2), "=r"(r3) : "r"(addr));
}
__device__ __forceinline__ void mma16816(float* c, const uint32_t* a, const uint32_t* b) {
    asm volatile("mma.sync.aligned.m16n8k16.row.col.f32.bf16.bf16.f32 "
                 "{%0,%1,%2,%3}, {%4,%5,%6,%7}, {%8,%9}, {%0,%1,%2,%3};"
                 : "+f"(c[0]), "+f"(c[1]), "+f"(c[2]), "+f"(c[3])
                 : "r"(a[0]), "r"(a[1]), "r"(a[2]), "r"(a[3]), "r"(b[0]), "r"(b[1]));
}

__device__ __forceinline__ unsigned int fkey(float f) {
    unsigned int u = __float_as_uint(f);
    return (u & 0x80000000u) ? ~u : (u | 0x80000000u);
}
__device__ __forceinline__ float inv_fkey(unsigned int k) {
    unsigned int u = (k & 0x80000000u) ? (k & 0x7fffffffu) : ~k;
    return __uint_as_float(u);
}

// ---------------- init ----------------
__global__ void init_kernel() {
    int i = blockIdx.x * blockDim.x + threadIdx.x;
    if (i < TOKENS) { g_minkey[i] = ~0ull; g_cndcnt[i] = 0; }
    if (i == 0) g_losssum = 0.0f;
}

// ---------------- codebook prep: bf16 hi + ||e||^2 ----------------
__global__ void prep_cb(const float* __restrict__ cb) {
    int warp = (blockIdx.x * blockDim.x + threadIdx.x) >> 5;
    int lane = threadIdx.x & 31;
    if (warp >= NCODES) return;
    size_t base = (size_t)warp * EDIM;
    float s = 0.0f;
#pragma unroll
    for (int i = 0; i < 8; i++) {
        int k = lane * 8 + i;
        float v = cb[base + k];
        g_ehi[base + k] = __float2bfloat16(v);
        s += v * v;
    }
#pragma unroll
    for (int o = 16; o; o >>= 1) s += __shfl_xor_sync(0xffffffffu, s, o);
    if (lane == 0) g_e2[warp] = s;
}

// ---------------- x split to bf16 hi/lo ----------------
__global__ void prep_x(const float* __restrict__ x) {
    int i4 = blockIdx.x * blockDim.x + threadIdx.x;   // float4 index
    if (i4 >= TOKENS * SRCDIM / 4) return;
    float4 v = ((const float4*)x)[i4];
    __nv_bfloat16 h0 = __float2bfloat16(v.x), h1 = __float2bfloat16(v.y);
    __nv_bfloat16 h2 = __float2bfloat16(v.z), h3 = __float2bfloat16(v.w);
    __nv_bfloat162* hi = (__nv_bfloat162*)g_xhi;
    __nv_bfloat162* lo = (__nv_bfloat162*)g_xlo;
    hi[i4 * 2]     = __nv_bfloat162(h0, h1);
    hi[i4 * 2 + 1] = __nv_bfloat162(h2, h3);
    lo[i4 * 2]     = __nv_bfloat162(__float2bfloat16(v.x - __bfloat162float(h0)),
                                    __float2bfloat16(v.y - __bfloat162float(h1)));
    lo[i4 * 2 + 1] = __nv_bfloat162(__float2bfloat16(v.z - __bfloat162float(h2)),
                                    __float2bfloat16(v.w - __bfloat162float(h3)));
}

// ---------------- enc_w transpose + split: [1024][256] -> [256][1024] hi/lo ----------------
__global__ void prep_ewt(const float* __restrict__ w) {
    __shared__ float t[32][33];
    int n0 = blockIdx.x * 32, k0 = blockIdx.y * 32;
    int tx = threadIdx.x, ty = threadIdx.y;
#pragma unroll
    for (int r = 0; r < 32; r += 8)
        t[ty + r][tx] = w[(size_t)(k0 + ty + r) * EDIM + n0 + tx];
    __syncthreads();
#pragma unroll
    for (int r = 0; r < 32; r += 8) {
        float v = t[tx][ty + r];   // w[k0+tx][n0+ty+r]
        __nv_bfloat16 h = __float2bfloat16(v);
        size_t o = (size_t)(n0 + ty + r) * SRCDIM + k0 + tx;
        g_ewhi[o] = h;
        g_ewlo[o] = __float2bfloat16(v - __bfloat162float(h));
    }
}

// ---------------- dec_w transpose to [n][k] bf16 ----------------
__global__ void prep_dwt(const float* __restrict__ dw) {
    __shared__ float t[32][33];
    int k0 = blockIdx.y * 32, n0 = blockIdx.x * 32;
    int tx = threadIdx.x, ty = threadIdx.y;
#pragma unroll
    for (int r = 0; r < 32; r += 8)
        t[ty + r][tx] = dw[(size_t)(k0 + ty + r) * SRCDIM + n0 + tx];
    __syncthreads();
#pragma unroll
    for (int r = 0; r < 32; r += 8)
        g_dwt[(size_t)(n0 + ty + r) * EDIM + k0 + tx] = __float2bfloat16(t[tx][ty + r]);
}

// [128 rows][64 k] tile loader, row 128B, XOR swizzle; rowstride in elements
__device__ __forceinline__ void load_tile64(uint32_t sdst, const __nv_bfloat16* gsrc,
                                            int rowstride, int tid) {
#pragma unroll
    for (int i = 0; i < 4; i++) {
        int q = tid + 256 * i;
        int r = q >> 3, c = q & 7;
        uint32_t dst = sdst + r * 128 + ((c ^ (r & 7)) << 4);
        cp_async16(dst, gsrc + (size_t)r * rowstride + c * 8);
    }
}

// ==================== encoder: z = x @ enc_w + b, split-bf16 3-term mma ====================
// SMEM: 2 stages x 64KB; stage: Ahi[0,16K) Alo[16K) Bhi[32K) Blo[48K)
#define EC_SMEM 131072

__global__ void __launch_bounds__(256, 1) enc_mma(const float* __restrict__ bias) {
    extern __shared__ char sm[];
    uint32_t sb = smem_u32(sm);
    int tid = threadIdx.x;
    int lane = tid & 31, wid = tid >> 5;
    int warp_m = wid & 1, warp_n = wid >> 1;
    int m0 = blockIdx.y * 128, n0 = blockIdx.x * 128;

    auto load_stage = [&](int c, int buf) {
        uint32_t base = sb + buf * 65536u;
        load_tile64(base,          g_xhi  + (size_t)m0 * SRCDIM + c * 64, SRCDIM, tid);
        load_tile64(base + 16384u, g_xlo  + (size_t)m0 * SRCDIM + c * 64, SRCDIM, tid);
        load_tile64(base + 32768u, g_ewhi + (size_t)n0 * SRCDIM + c * 64, SRCDIM, tid);
        load_tile64(base + 49152u, g_ewlo + (size_t)n0 * SRCDIM + c * 64, SRCDIM, tid);
    };

    float acc[4][4][4];
#pragma unroll
    for (int i = 0; i < 4; i++)
#pragma unroll
        for (int j = 0; j < 4; j++)
#pragma unroll
            for (int q = 0; q < 4; q++) acc[i][j][q] = 0.0f;

    load_stage(0, 0);
    cp_commit();

    for (int c = 0; c < 16; c++) {
        if (c < 15) { load_stage(c + 1, (c + 1) & 1); cp_commit(); cp_wait1(); }
        else cp_wait0();
        __syncthreads();

        uint32_t base = sb + (c & 1) * 65536u;
        uint32_t Ah = base, Al = base + 16384u, Bh = base + 32768u, Bl = base + 49152u;
#pragma unroll
        for (int kk = 0; kk < 4; kk++) {
            uint32_t bh[2][4], bl[2][4];
#pragma unroll
            for (int jp = 0; jp < 2; jp++) {
                int n = warp_n * 32 + jp * 16 + (lane & 7) + ((lane >> 4) << 3);
                int ch = kk * 2 + ((lane >> 3) & 1);
                uint32_t sw = ((ch ^ (n & 7)) << 4);
                ldsm_x4(bh[jp][0], bh[jp][1], bh[jp][2], bh[jp][3], Bh + n * 128 + sw);
                ldsm_x4(bl[jp][0], bl[jp][1], bl[jp][2], bl[jp][3], Bl + n * 128 + sw);
            }
#pragma unroll
            for (int i = 0; i < 4; i++) {
                int r = warp_m * 64 + i * 16 + (lane & 15);
                int kb = kk * 2 + (lane >> 4);
                uint32_t sw = ((kb ^ (r & 7)) << 4);
                uint32_t ah[4], al[4];
                ldsm_x4(ah[0], ah[1], ah[2], ah[3], Ah + r * 128 + sw);
                ldsm_x4(al[0], al[1], al[2], al[3], Al + r * 128 + sw);
#pragma unroll
                for (int j = 0; j < 4; j++) {
                    mma16816(acc[i][j], ah, &bh[j >> 1][(j & 1) * 2]);
                    mma16816(acc[i][j], al, &bh[j >> 1][(j & 1) * 2]);
                    mma16816(acc[i][j], ah, &bl[j >> 1][(j & 1) * 2]);
                }
            }
        }
        __syncthreads();
    }

    // epilogue: bias, write z fp32 + z_hi bf16
#pragma unroll
    for (int j = 0; j < 4; j++) {
        int n = n0 + warp_n * 32 + j * 8 + (lane & 3) * 2;
        float b0 = bias[n], b1 = bias[n + 1];
#pragma unroll
        for (int i = 0; i < 4; i++) {
            int row = m0 + warp_m * 64 + i * 16 + (lane >> 2);
#pragma unroll
            for (int q = 0; q < 2; q++) {
                int rr = row + q * 8;
                float v0 = acc[i][j][q * 2] + b0;
                float v1 = acc[i][j][q * 2 + 1] + b1;
                *(float2*)(g_z + (size_t)rr * EDIM + n) = make_float2(v0, v1);
                *(__nv_bfloat162*)(g_zhi + (size_t)rr * EDIM + n) =
                    __nv_bfloat162(__float2bfloat16(v0), __float2bfloat16(v1));
            }
        }
    }
}

// ==================== score phase 1: hi*hi mma + candidate collection ====================
// SMEM: A zhi [0,64K) row 512B swizzled; B stages 2x16K [64K,96K); e2 [96K,+512); mk u64[128]
#define SCB_OFF  65536
#define SCE2_OFF 98304
#define SCMK_OFF 98816
#define SC_SMEM  99840

__device__ __forceinline__ void load_b_stage(uint32_t sdst, const __nv_bfloat16* gsrc, int tid) {
#pragma unroll
    for (int i = 0; i < 4; i++) {
        int q = tid + 256 * i;
        int r = q >> 3, c = q & 7;
        uint32_t dst = sdst + r * 128 + ((c ^ (r & 7)) << 4);
        cp_async16(dst, gsrc + (size_t)r * 256 + c * 8);
    }
}

__global__ void __launch_bounds__(256, 1) score_p1() {
    extern __shared__ char sm[];
    uint32_t sb = smem_u32(sm);
    int tid = threadIdx.x;
    int lane = tid & 31, wid = tid >> 5;
    int warp_m = wid & 1, warp_n = wid >> 1;
    int m0 = blockIdx.y * 128;

    unsigned long long* mk = (unsigned long long*)(sm + SCMK_OFF);
    float* e2s = (float*)(sm + SCE2_OFF);
    if (tid < 128) mk[tid] = ~0ull;

    // persistent A (zhi)
    {
        const __nv_bfloat16* zh = g_zhi + (size_t)m0 * 256;
#pragma unroll
        for (int i = 0; i < 16; i++) {
            int q = tid + 256 * i;
            int r = q >> 5, c = q & 31;
            uint32_t dst = sb + r * 512 + (c >> 3) * 128 + (((c & 7) ^ (r & 7)) << 4);
            cp_async16(dst, zh + (size_t)r * 256 + c * 8);
        }
        cp_commit();
        cp_wait0();
    }
    __syncthreads();

    float acc[4][4][4];
#pragma unroll
    for (int i = 0; i < 4; i++)
#pragma unroll
        for (int j = 0; j < 4; j++)
#pragma unroll
            for (int q = 0; q < 4; q++) acc[i][j][q] = 0.0f;

    // prefetch tile 0 chunk 0
    load_b_stage(sb + SCB_OFF, g_ehi + (size_t)(blockIdx.x * 64) * 128 * 256, tid);
    cp_commit();

    for (int t = 0; t < 64; t++) {
        int n0 = (blockIdx.x * 64 + t) * 128;
        if (tid < 128) e2s[tid] = g_e2[n0 + tid];

        for (int st = 0; st < 4; st++) {
            bool last = (t == 63 && st == 3);
            if (!last) {
                const __nv_bfloat16* src = (st < 3)
                    ? g_ehi + (size_t)n0 * 256 + (st + 1) * 64
                    : g_ehi + (size_t)(n0 + 128) * 256;   // next tile chunk 0
                load_b_stage(sb + SCB_OFF + ((st + 1) & 1) * 16384, src, tid);
                cp_commit();
                cp_wait1();
            } else cp_wait0();
            __syncthreads();

            uint32_t bbase = sb + SCB_OFF + (st & 1) * 16384;
#pragma unroll
            for (int kk = 0; kk < 4; kk++) {
                uint32_t b[2][4];
#pragma unroll
                for (int jp = 0; jp < 2; jp++) {
                    int n = warp_n * 32 + jp * 16 + (lane & 7) + ((lane >> 4) << 3);
                    int ch = kk * 2 + ((lane >> 3) & 1);
                    ldsm_x4(b[jp][0], b[jp][1], b[jp][2], b[jp][3],
                            bbase + n * 128 + ((ch ^ (n & 7)) << 4));
                }
#pragma unroll
                for (int i = 0; i < 4; i++) {
                    int r = warp_m * 64 + i * 16 + (lane & 15);
                    int k = st * 64 + kk * 16 + ((lane >> 4) << 3);
                    int c32 = k >> 3;
                    uint32_t ad = sb + r * 512 + (c32 >> 3) * 128 +
                                  (((c32 & 7) ^ (r & 7)) << 4);
                    uint32_t a[4];
                    ldsm_x4(a[0], a[1], a[2], a[3], ad);
#pragma unroll
                    for (int j = 0; j < 4; j++)
                        mma16816(acc[i][j], a, &b[j >> 1][(j & 1) * 2]);
                }
            }
            __syncthreads();
        }

        // ---- epilogue pass 1: scores + per-row running min ----
        float e2r[8];
#pragma unroll
        for (int j = 0; j < 4; j++) {
            int nl = warp_n * 32 + j * 8 + (lane & 3) * 2;
            e2r[j * 2] = e2s[nl];
            e2r[j * 2 + 1] = e2s[nl + 1];
        }
#pragma unroll
        for (int i = 0; i < 4; i++) {
#pragma unroll
            for (int half = 0; half < 2; half++) {
                float best = __int_as_float(0x7f800000);
                int bn = 0;
#pragma unroll
                for (int j = 0; j < 4; j++) {
#pragma unroll
                    for (int jj = 0; jj < 2; jj++) {
                        float s = fmaf(-2.0f, acc[i][j][half * 2 + jj], e2r[j * 2 + jj]);
                        acc[i][j][half * 2 + jj] = s;
                        int nl = warp_n * 32 + j * 8 + (lane & 3) * 2 + jj;
                        if (s < best) { best = s; bn = nl; }
                    }
                }
                unsigned long long key =
                    ((unsigned long long)fkey(best) << 32) | (unsigned int)(n0 + bn);
                unsigned long long o = __shfl_xor_sync(0xffffffffu, key, 1);
                if (o < key) key = o;
                o = __shfl_xor_sync(0xffffffffu, key, 2);
                if (o < key) key = o;
                if ((lane & 3) == 0)
                    atomicMin(&mk[warp_m * 64 + i * 16 + (lane >> 2) + half * 8], key);
            }
        }
        __syncthreads();
        // ---- epilogue pass 2: candidate collection ----
#pragma unroll
        for (int i = 0; i < 4; i++) {
#pragma unroll
            for (int half = 0; half < 2; half++) {
                int rowl = warp_m * 64 + i * 16 + (lane >> 2) + half * 8;
                float thresh = inv_fkey((unsigned int)(mk[rowl] >> 32)) + TAU;
                int rowg = m0 + rowl;
#pragma unroll
                for (int j = 0; j < 4; j++) {
#pragma unroll
                    for (int jj = 0; jj < 2; jj++) {
                        float s = acc[i][j][half * 2 + jj];
                        acc[i][j][half * 2 + jj] = 0.0f;
                        if (s < thresh) {
                            int n = n0 + warp_n * 32 + j * 8 + (lane & 3) * 2 + jj;
                            int pos = atomicAdd(&g_cndcnt[rowg], 1);
                            if (pos < CAP) g_cand[rowg * CAP + pos] = (unsigned int)n;
                        }
                    }
                }
            }
        }
        __syncthreads();
    }
    if (tid < 128) atomicMin(&g_minkey[m0 + tid], mk[tid]);
}

// ==================== refine: exact fp32 rescore of candidates ====================
__global__ void __launch_bounds__(256) refine_kernel(const float* __restrict__ cb) {
    int gw = (blockIdx.x * 256 + threadIdx.x) >> 5;
    int lane = threadIdx.x & 31;
    if (gw >= TOKENS) return;
    const float4* z = (const float4*)(g_z + (size_t)gw * 256);
    float4 z0 = z[lane * 2], z1 = z[lane * 2 + 1];
    int cnt = g_cndcnt[gw];
    if (cnt > CAP) cnt = CAP;
    unsigned long long best = ~0ull;
    int idx0 = (int)(g_minkey[gw] & 0xffffffffu);
    for (int c = -1; c < cnt; c++) {
        int idx = (c < 0) ? idx0 : (int)g_cand[gw * CAP + c];
        const float4* e = (const float4*)(cb + (size_t)idx * 256);
        float4 e0 = e[lane * 2], e1 = e[lane * 2 + 1];
        float d = z0.x * e0.x + z0.y * e0.y + z0.z * e0.z + z0.w * e0.w
                + z1.x * e1.x + z1.y * e1.y + z1.z * e1.z + z1.w * e1.w;
#pragma unroll
        for (int o = 16; o; o >>= 1) d += __shfl_xor_sync(0xffffffffu, d, o);
        float s = fmaf(-2.0f, d, g_e2[idx]);
        unsigned long long key = ((unsigned long long)fkey(s) << 32) | (unsigned int)idx;
        if (key < best) best = key;
    }
    if (lane == 0) g_minkey[gw] = best;
}

// ==================== decoder: out = ehi[idx] @ dwt^T + dec_b ====================
#define DCB_OFF  65536
#define DCI_OFF  98304
#define DC_SMEM  98816

__global__ void __launch_bounds__(256, 2) dec_kernel(const float* __restrict__ bias,
                                                     float* __restrict__ C) {
    extern __shared__ char sm[];
    uint32_t sb = smem_u32(sm);
    int tid = threadIdx.x;
    int lane = tid & 31, wid = tid >> 5;
    int warp_m = wid & 1, warp_n = wid >> 1;
    int m0 = blockIdx.y * 128, n0 = blockIdx.x * 128;

    int* idxs = (int*)(sm + DCI_OFF);
    if (tid < 128) idxs[tid] = (int)(g_minkey[m0 + tid] & 0xffffffffu);
    __syncthreads();

#pragma unroll
    for (int i = 0; i < 16; i++) {
        int q = tid + 256 * i;
        int r = q >> 5, c = q & 31;
        uint32_t dst = sb + r * 512 + (c >> 3) * 128 + (((c & 7) ^ (r & 7)) << 4);
        cp_async16(dst, g_ehi + (size_t)idxs[r] * 256 + c * 8);
    }
    cp_commit();
    load_b_stage(sb + DCB_OFF, g_dwt + (size_t)n0 * 256, tid);
    cp_commit();

    float acc[4][4][4];
#pragma unroll
    for (int i = 0; i < 4; i++)
#pragma unroll
        for (int j = 0; j < 4; j++)
#pragma unroll
            for (int q = 0; q < 4; q++) acc[i][j][q] = 0.0f;

    for (int st = 0; st < 4; st++) {
        if (st < 3) {
            load_b_stage(sb + DCB_OFF + ((st + 1) & 1) * 16384,
                         g_dwt + (size_t)n0 * 256 + (st + 1) * 64, tid);
            cp_commit();
            cp_wait1();
        } else cp_wait0();
        __syncthreads();

        uint32_t bbase = sb + DCB_OFF + (st & 1) * 16384;
#pragma unroll
        for (int kk = 0; kk < 4; kk++) {
            uint32_t b[2][4];
#pragma unroll
            for (int jp = 0; jp < 2; jp++) {
                int n = warp_n * 32 + jp * 16 + (lane & 7) + ((lane >> 4) << 3);
                int ch = kk * 2 + ((lane >> 3) & 1);
                ldsm_x4(b[jp][0], b[jp][1], b[jp][2], b[jp][3],
                        bbase + n * 128 + ((ch ^ (n & 7)) << 4));
            }
#pragma unroll
            for (int i = 0; i < 4; i++) {
                int r = warp_m * 64 + i * 16 + (lane & 15);
                int k = st * 64 + kk * 16 + ((lane >> 4) << 3);
                int c32 = k >> 3;
                uint32_t ad = sb + r * 512 + (c32 >> 3) * 128 + (((c32 & 7) ^ (r & 7)) << 4);
                uint32_t a[4];
                ldsm_x4(a[0], a[1], a[2], a[3], ad);
#pragma unroll
                for (int j = 0; j < 4; j++)
                    mma16816(acc[i][j], a, &b[j >> 1][(j & 1) * 2]);
            }
        }
        __syncthreads();
    }

#pragma unroll
    for (int j = 0; j < 4; j++) {
        int n = n0 + warp_n * 32 + j * 8 + (lane & 3) * 2;
        float b0 = bias[n], b1 = bias[n + 1];
#pragma unroll
        for (int i = 0; i < 4; i++) {
            int row = m0 + warp_m * 64 + i * 16 + (lane >> 2);
            *(float2*)(C + (size_t)row * SRCDIM + n) =
                make_float2(acc[i][j][0] + b0, acc[i][j][1] + b1);
            *(float2*)(C + (size_t)(row + 8) * SRCDIM + n) =
                make_float2(acc[i][j][2] + b0, acc[i][j][3] + b1);
        }
    }
}

// ---------------- loss = 1.25 * mean((z_q - z)^2) ----------------
__global__ void loss_kernel(const float* __restrict__ cb) {
    __shared__ float red[256];
    int tid = threadIdx.x;
    float part = 0.0f;
    const int total = TOKENS * EDIM;
    for (int i = blockIdx.x * blockDim.x + tid; i < total; i += gridDim.x * blockDim.x) {
        int t = i >> 8;
        int id = (int)(g_minkey[t] & 0xffffffffu);
        float d = cb[(size_t)id * EDIM + (i & 255)] - g_z[i];
        part += d * d;
    }
    red[tid] = part;
    __syncthreads();
    for (int s = 128; s; s >>= 1) {
        if (tid < s) red[tid] += red[tid + s];
        __syncthreads();
    }
    if (tid == 0) atomicAdd(&g_losssum, red[0]);
}

__global__ void finalize_kernel(float* __restrict__ out, int n) {
    out[n - 1] = 1.25f * g_losssum / (float)(TOKENS * EDIM);
}

// ---------------- launch ----------------
extern "C" void kernel_launch(void* const* d_in, const int* in_sizes, int n_in,
                              void* d_out, int out_size) {
    const float* x     = (const float*)d_in[0];
    const float* enc_w = (const float*)d_in[1];
    const float* enc_b = (const float*)d_in[2];
    const float* cb    = (const float*)d_in[3];
    const float* dec_w = (const float*)d_in[4];
    const float* dec_b = (const float*)d_in[5];
    float* out = (float*)d_out;

    static bool attr_done = false;
    if (!attr_done) {
        cudaFuncSetAttribute(enc_mma, cudaFuncAttributeMaxDynamicSharedMemorySize, EC_SMEM);
        cudaFuncSetAttribute(score_p1, cudaFuncAttributeMaxDynamicSharedMemorySize, SC_SMEM);
        cudaFuncSetAttribute(dec_kernel, cudaFuncAttributeMaxDynamicSharedMemorySize, DC_SMEM);
        attr_done = true;
    }

    init_kernel<<<(TOKENS + 255) / 256, 256>>>();
    prep_cb<<<(NCODES * 32) / 256, 256>>>(cb);
    prep_x<<<TOKENS * SRCDIM / 4 / 256, 256>>>(x);
    prep_ewt<<<dim3(EDIM / 32, SRCDIM / 32), dim3(32, 8)>>>(enc_w);
    prep_dwt<<<dim3(SRCDIM / 32, EDIM / 32), dim3(32, 8)>>>(dec_w);
    enc_mma<<<dim3(EDIM / 128, TOKENS / 128), 256, EC_SMEM>>>(enc_b);
    score_p1<<<dim3(2, TOKENS / 128), 256, SC_SMEM>>>();
    refine_kernel<<<(TOKENS * 32 + 255) / 256, 256>>>(cb);
    dec_kernel<<<dim3(SRCDIM / 128, TOKENS / 128), 256, DC_SMEM>>>(dec_b, out);
    loss_kernel<<<296, 256>>>(cb);
    finalize_kernel<<<1, 1>>>(out, out_size);
}

// round 5
// speedup vs baseline: 4.3958x; 1.1113x over previous
#include <cuda_runtime.h>
#include <cuda_bf16.h>
#include <cstdint>

#define TOKENS 9216
#define EDIM 256
#define SRCDIM 1024
#define NCODES 16384
#define CAP 128
#define TAU 3e-5f

// ---------------- device scratch ----------------
__device__ float g_z[TOKENS * EDIM];
__device__ __nv_bfloat16 g_zhi[TOKENS * EDIM];
__device__ __nv_bfloat16 g_ehi[NCODES * EDIM];
__device__ __nv_bfloat16 g_xhi[TOKENS * SRCDIM];
__device__ __nv_bfloat16 g_xlo[TOKENS * SRCDIM];
__device__ __nv_bfloat16 g_ewhi[EDIM * SRCDIM];   // enc_w^T hi [n][k]
__device__ __nv_bfloat16 g_ewlo[EDIM * SRCDIM];   // enc_w^T lo
__device__ __nv_bfloat16 g_dwt[SRCDIM * EDIM];    // dec_w^T bf16 [n][k]
__device__ float g_e2[NCODES];
__device__ unsigned long long g_minkey[TOKENS];
__device__ int g_cndcnt[TOKENS];
__device__ unsigned int g_cand[TOKENS * CAP];
__device__ float g_losssum;

// ---------------- portable PTX helpers ----------------
__device__ __forceinline__ uint32_t smem_u32(const void* p) {
    uint32_t a;
    asm("{ .reg .u64 t; cvta.to.shared.u64 t, %1; cvt.u32.u64 %0, t; }" : "=r"(a) : "l"(p));
    return a;
}
__device__ __forceinline__ void cp_async16(uint32_t dst, const void* src) {
    asm volatile("cp.async.cg.shared.global [%0], [%1], 16;" :: "r"(dst), "l"(src) : "memory");
}
__device__ __forceinline__ void cp_commit() { asm volatile("cp.async.commit_group;" ::: "memory"); }
__device__ __forceinline__ void cp_wait0() { asm volatile("cp.async.wait_group 0;" ::: "memory"); }
__device__ __forceinline__ void cp_wait1() { asm volatile("cp.async.wait_group 1;" ::: "memory"); }
__device__ __forceinline__ void cp_wait2() { asm volatile("cp.async.wait_group 2;" ::: "memory"); }

__device__ __forceinline__ void ldsm_x4(uint32_t& r0, uint32_t& r1, uint32_t& r2, uint32_t& r3,
                                        uint32_t addr) {
    asm volatile("ldmatrix.sync.aligned.m8n8.x4.shared.b16 {%0,%1,%2,%3}, [%4];"
                 : "=r"(r0), "=r"(r1), "=r"(r2), "=r"(r3) : "r"(addr));
}
__device__ __forceinline__ void mma16816(float* c, const uint32_t* a, const uint32_t* b) {
    asm volatile("mma.sync.aligned.m16n8k16.row.col.f32.bf16.bf16.f32 "
                 "{%0,%1,%2,%3}, {%4,%5,%6,%7}, {%8,%9}, {%0,%1,%2,%3};"
                 : "+f"(c[0]), "+f"(c[1]), "+f"(c[2]), "+f"(c[3])
                 : "r"(a[0]), "r"(a[1]), "r"(a[2]), "r"(a[3]), "r"(b[0]), "r"(b[1]));
}

__device__ __forceinline__ unsigned int fkey(float f) {
    unsigned int u = __float_as_uint(f);
    return (u & 0x80000000u) ? ~u : (u | 0x80000000u);
}
__device__ __forceinline__ float inv_fkey(unsigned int k) {
    unsigned int u = (k & 0x80000000u) ? (k & 0x7fffffffu) : ~k;
    return __uint_as_float(u);
}

// ==================== fused prep: init + cb split + x split + w transposes ====================
// grid 4096 x 256:
//   [0,256)     enc_w^T + hi/lo split
//   [256,512)   dec_w^T bf16
//   [512,2560)  codebook bf16-hi + e2 (warp/code) + minkey/cnt init
//   [2560,4096) x hi/lo split (grid-stride)
__global__ void __launch_bounds__(256) prep_all(const float* __restrict__ x,
                                                const float* __restrict__ enc_w,
                                                const float* __restrict__ cb,
                                                const float* __restrict__ dec_w) {
    __shared__ float t[32][33];
    int b = blockIdx.x, tid = threadIdx.x;
    int tx = tid & 31, ty = tid >> 5;

    if (b < 256) {
        int n0 = (b & 7) * 32, k0 = (b >> 3) * 32;
#pragma unroll
        for (int r = 0; r < 32; r += 8)
            t[ty + r][tx] = enc_w[(size_t)(k0 + ty + r) * EDIM + n0 + tx];
        __syncthreads();
#pragma unroll
        for (int r = 0; r < 32; r += 8) {
            float v = t[tx][ty + r];
            __nv_bfloat16 h = __float2bfloat16(v);
            size_t o = (size_t)(n0 + ty + r) * SRCDIM + k0 + tx;
            g_ewhi[o] = h;
            g_ewlo[o] = __float2bfloat16(v - __bfloat162float(h));
        }
    } else if (b < 512) {
        int idx = b - 256;
        int n0 = (idx & 31) * 32, k0 = (idx >> 5) * 32;
#pragma unroll
        for (int r = 0; r < 32; r += 8)
            t[ty + r][tx] = dec_w[(size_t)(k0 + ty + r) * SRCDIM + n0 + tx];
        __syncthreads();
#pragma unroll
        for (int r = 0; r < 32; r += 8)
            g_dwt[(size_t)(n0 + ty + r) * EDIM + k0 + tx] = __float2bfloat16(t[tx][ty + r]);
    } else if (b < 2560) {
        int bb = b - 512;
        int i = bb * 256 + tid;
        if (i < TOKENS) { g_minkey[i] = ~0ull; g_cndcnt[i] = 0; }
        if (i == 0) g_losssum = 0.0f;
        int warp = bb * 8 + (tid >> 5);     // exactly 16384 warps
        int lane = tid & 31;
        size_t base = (size_t)warp * EDIM;
        float s = 0.0f;
#pragma unroll
        for (int q = 0; q < 8; q++) {
            int k = lane * 8 + q;
            float v = cb[base + k];
            g_ehi[base + k] = __float2bfloat16(v);
            s += v * v;
        }
#pragma unroll
        for (int o = 16; o; o >>= 1) s += __shfl_xor_sync(0xffffffffu, s, o);
        if (lane == 0) g_e2[warp] = s;
    } else {
        const int total4 = TOKENS * SRCDIM / 4;
        for (int i4 = (b - 2560) * 256 + tid; i4 < total4; i4 += 1536 * 256) {
            float4 v = ((const float4*)x)[i4];
            __nv_bfloat16 h0 = __float2bfloat16(v.x), h1 = __float2bfloat16(v.y);
            __nv_bfloat16 h2 = __float2bfloat16(v.z), h3 = __float2bfloat16(v.w);
            __nv_bfloat162* hi = (__nv_bfloat162*)g_xhi;
            __nv_bfloat162* lo = (__nv_bfloat162*)g_xlo;
            hi[i4 * 2]     = __nv_bfloat162(h0, h1);
            hi[i4 * 2 + 1] = __nv_bfloat162(h2, h3);
            lo[i4 * 2]     = __nv_bfloat162(__float2bfloat16(v.x - __bfloat162float(h0)),
                                            __float2bfloat16(v.y - __bfloat162float(h1)));
            lo[i4 * 2 + 1] = __nv_bfloat162(__float2bfloat16(v.z - __bfloat162float(h2)),
                                            __float2bfloat16(v.w - __bfloat162float(h3)));
        }
    }
}

// [128 rows][64 k] tile loader, row 128B, XOR swizzle
__device__ __forceinline__ void load_tile64(uint32_t sdst, const __nv_bfloat16* gsrc,
                                            int rowstride, int tid) {
#pragma unroll
    for (int i = 0; i < 4; i++) {
        int q = tid + 256 * i;
        int r = q >> 3, c = q & 7;
        uint32_t dst = sdst + r * 128 + ((c ^ (r & 7)) << 4);
        cp_async16(dst, gsrc + (size_t)r * rowstride + c * 8);
    }
}

// ==================== encoder: z = x @ enc_w + b, split-bf16 3-term mma ====================
#define EC_SMEM 131072

__global__ void __launch_bounds__(256, 1) enc_mma(const float* __restrict__ bias) {
    extern __shared__ char sm[];
    uint32_t sb = smem_u32(sm);
    int tid = threadIdx.x;
    int lane = tid & 31, wid = tid >> 5;
    int warp_m = wid & 1, warp_n = wid >> 1;
    int m0 = blockIdx.y * 128, n0 = blockIdx.x * 128;

    auto load_stage = [&](int c, int buf) {
        uint32_t base = sb + buf * 65536u;
        load_tile64(base,          g_xhi  + (size_t)m0 * SRCDIM + c * 64, SRCDIM, tid);
        load_tile64(base + 16384u, g_xlo  + (size_t)m0 * SRCDIM + c * 64, SRCDIM, tid);
        load_tile64(base + 32768u, g_ewhi + (size_t)n0 * SRCDIM + c * 64, SRCDIM, tid);
        load_tile64(base + 49152u, g_ewlo + (size_t)n0 * SRCDIM + c * 64, SRCDIM, tid);
    };

    float acc[4][4][4];
#pragma unroll
    for (int i = 0; i < 4; i++)
#pragma unroll
        for (int j = 0; j < 4; j++)
#pragma unroll
            for (int q = 0; q < 4; q++) acc[i][j][q] = 0.0f;

    load_stage(0, 0);
    cp_commit();

    for (int c = 0; c < 16; c++) {
        if (c < 15) { load_stage(c + 1, (c + 1) & 1); cp_commit(); cp_wait1(); }
        else cp_wait0();
        __syncthreads();

        uint32_t base = sb + (c & 1) * 65536u;
        uint32_t Ah = base, Al = base + 16384u, Bh = base + 32768u, Bl = base + 49152u;
#pragma unroll
        for (int kk = 0; kk < 4; kk++) {
            uint32_t bh[2][4], bl[2][4];
#pragma unroll
            for (int jp = 0; jp < 2; jp++) {
                int n = warp_n * 32 + jp * 16 + (lane & 7) + ((lane >> 4) << 3);
                int ch = kk * 2 + ((lane >> 3) & 1);
                uint32_t sw = ((ch ^ (n & 7)) << 4);
                ldsm_x4(bh[jp][0], bh[jp][1], bh[jp][2], bh[jp][3], Bh + n * 128 + sw);
                ldsm_x4(bl[jp][0], bl[jp][1], bl[jp][2], bl[jp][3], Bl + n * 128 + sw);
            }
#pragma unroll
            for (int i = 0; i < 4; i++) {
                int r = warp_m * 64 + i * 16 + (lane & 15);
                int kb = kk * 2 + (lane >> 4);
                uint32_t sw = ((kb ^ (r & 7)) << 4);
                uint32_t ah[4], al[4];
                ldsm_x4(ah[0], ah[1], ah[2], ah[3], Ah + r * 128 + sw);
                ldsm_x4(al[0], al[1], al[2], al[3], Al + r * 128 + sw);
#pragma unroll
                for (int j = 0; j < 4; j++) {
                    mma16816(acc[i][j], ah, &bh[j >> 1][(j & 1) * 2]);
                    mma16816(acc[i][j], al, &bh[j >> 1][(j & 1) * 2]);
                    mma16816(acc[i][j], ah, &bl[j >> 1][(j & 1) * 2]);
                }
            }
        }
        __syncthreads();
    }

#pragma unroll
    for (int j = 0; j < 4; j++) {
        int n = n0 + warp_n * 32 + j * 8 + (lane & 3) * 2;
        float b0 = bias[n], b1 = bias[n + 1];
#pragma unroll
        for (int i = 0; i < 4; i++) {
            int row = m0 + warp_m * 64 + i * 16 + (lane >> 2);
#pragma unroll
            for (int q = 0; q < 2; q++) {
                int rr = row + q * 8;
                float v0 = acc[i][j][q * 2] + b0;
                float v1 = acc[i][j][q * 2 + 1] + b1;
                *(float2*)(g_z + (size_t)rr * EDIM + n) = make_float2(v0, v1);
                *(__nv_bfloat162*)(g_zhi + (size_t)rr * EDIM + n) =
                    __nv_bfloat162(__float2bfloat16(v0), __float2bfloat16(v1));
            }
        }
    }
}

// ==================== score phase 1: CTA 128x256, warp 64x64, 3-stage pipeline ====================
// SMEM: A zhi [0,64K) row 512B swizzled; B 3 x 32KB [64K,160K); e2[256] ; mk u64[128]
#define SCB_OFF  65536
#define SCE2_OFF 163840
#define SCMK_OFF 164864
#define SC_SMEM  165888
#define NCHUNKS  128          // 32 tiles x 4 k-chunks

__global__ void __launch_bounds__(256, 1) score_p1() {
    extern __shared__ char sm[];
    uint32_t sb = smem_u32(sm);
    int tid = threadIdx.x;
    int lane = tid & 31, wid = tid >> 5;
    int warp_m = wid & 1, warp_n = wid >> 1;
    int m0 = blockIdx.y * 128;
    int nbase = blockIdx.x * 8192;

    unsigned long long* mk = (unsigned long long*)(sm + SCMK_OFF);
    float* e2s = (float*)(sm + SCE2_OFF);
    if (tid < 128) mk[tid] = ~0ull;

    // persistent A (zhi) — cp.async group 0
    {
        const __nv_bfloat16* zh = g_zhi + (size_t)m0 * 256;
#pragma unroll
        for (int i = 0; i < 16; i++) {
            int q = tid + 256 * i;
            int r = q >> 5, c = q & 31;
            uint32_t dst = sb + r * 512 + (c >> 3) * 128 + (((c & 7) ^ (r & 7)) << 4);
            cp_async16(dst, zh + (size_t)r * 256 + c * 8);
        }
        cp_commit();
    }

    // B chunk loader: chunk c -> tile c>>2, k-seg c&3, buf c%3 (256 rows x 64 k)
    auto load_chunk = [&](int c) {
        uint32_t sdst = sb + SCB_OFF + (uint32_t)(c % 3) * 32768u;
        const __nv_bfloat16* gsrc =
            g_ehi + (size_t)(nbase + (c >> 2) * 256) * 256 + (c & 3) * 64;
#pragma unroll
        for (int i = 0; i < 8; i++) {
            int q = tid + 256 * i;
            int r = q >> 3, cc = q & 7;
            uint32_t dst = sdst + r * 128 + ((cc ^ (r & 7)) << 4);
            cp_async16(dst, gsrc + (size_t)r * 256 + cc * 8);
        }
    };

    load_chunk(0); cp_commit();
    load_chunk(1); cp_commit();

    float acc[4][8][4];
#pragma unroll
    for (int i = 0; i < 4; i++)
#pragma unroll
        for (int j = 0; j < 8; j++)
#pragma unroll
            for (int q = 0; q < 4; q++) acc[i][j][q] = 0.0f;

    for (int c = 0; c < NCHUNKS; c++) {
        if ((c & 3) == 0) e2s[tid] = g_e2[nbase + (c >> 2) * 256 + tid];
        if (c + 2 < NCHUNKS) { load_chunk(c + 2); cp_commit(); }
        int rem = NCHUNKS - 1 - c;
        if (rem >= 2) cp_wait2(); else if (rem == 1) cp_wait1(); else cp_wait0();
        __syncthreads();

        uint32_t bbase = sb + SCB_OFF + (uint32_t)(c % 3) * 32768u;
        int kst = (c & 3) * 64;
#pragma unroll
        for (int kk = 0; kk < 4; kk++) {
            uint32_t bf[4][4];
#pragma unroll
            for (int jp = 0; jp < 4; jp++) {
                int n = warp_n * 64 + jp * 16 + (lane & 7) + ((lane >> 4) << 3);
                int ch = kk * 2 + ((lane >> 3) & 1);
                ldsm_x4(bf[jp][0], bf[jp][1], bf[jp][2], bf[jp][3],
                        bbase + n * 128 + ((ch ^ (n & 7)) << 4));
            }
#pragma unroll
            for (int i = 0; i < 4; i++) {
                int r = warp_m * 64 + i * 16 + (lane & 15);
                int k = kst + kk * 16 + ((lane >> 4) << 3);
                int c32 = k >> 3;
                uint32_t ad = sb + r * 512 + (c32 >> 3) * 128 + (((c32 & 7) ^ (r & 7)) << 4);
                uint32_t a[4];
                ldsm_x4(a[0], a[1], a[2], a[3], ad);
#pragma unroll
                for (int j = 0; j < 8; j++)
                    mma16816(acc[i][j], a, &bf[j >> 1][(j & 1) * 2]);
            }
        }

        if ((c & 3) == 3) {
            int n0 = nbase + (c >> 2) * 256;
            float e2r[16];
#pragma unroll
            for (int j = 0; j < 8; j++) {
                int nl = warp_n * 64 + j * 8 + (lane & 3) * 2;
                e2r[j * 2] = e2s[nl];
                e2r[j * 2 + 1] = e2s[nl + 1];
            }
            // pass 1: running min
#pragma unroll
            for (int i = 0; i < 4; i++) {
#pragma unroll
                for (int half = 0; half < 2; half++) {
                    float best = __int_as_float(0x7f800000);
                    int bn = 0;
#pragma unroll
                    for (int j = 0; j < 8; j++) {
#pragma unroll
                        for (int jj = 0; jj < 2; jj++) {
                            float s = fmaf(-2.0f, acc[i][j][half * 2 + jj], e2r[j * 2 + jj]);
                            acc[i][j][half * 2 + jj] = s;
                            int nl = warp_n * 64 + j * 8 + (lane & 3) * 2 + jj;
                            if (s < best) { best = s; bn = nl; }
                        }
                    }
                    unsigned long long key =
                        ((unsigned long long)fkey(best) << 32) | (unsigned int)(n0 + bn);
                    unsigned long long o = __shfl_xor_sync(0xffffffffu, key, 1);
                    if (o < key) key = o;
                    o = __shfl_xor_sync(0xffffffffu, key, 2);
                    if (o < key) key = o;
                    if ((lane & 3) == 0)
                        atomicMin(&mk[warp_m * 64 + i * 16 + (lane >> 2) + half * 8], key);
                }
            }
            __syncthreads();
            // pass 2: candidate collection
#pragma unroll
            for (int i = 0; i < 4; i++) {
#pragma unroll
                for (int half = 0; half < 2; half++) {
                    int rowl = warp_m * 64 + i * 16 + (lane >> 2) + half * 8;
                    float thresh = inv_fkey((unsigned int)(mk[rowl] >> 32)) + TAU;
                    int rowg = m0 + rowl;
#pragma unroll
                    for (int j = 0; j < 8; j++) {
#pragma unroll
                        for (int jj = 0; jj < 2; jj++) {
                            float s = acc[i][j][half * 2 + jj];
                            acc[i][j][half * 2 + jj] = 0.0f;
                            if (s < thresh) {
                                int n = n0 + warp_n * 64 + j * 8 + (lane & 3) * 2 + jj;
                                int pos = atomicAdd(&g_cndcnt[rowg], 1);
                                if (pos < CAP) g_cand[rowg * CAP + pos] = (unsigned int)n;
                            }
                        }
                    }
                }
            }
        }
        __syncthreads();
    }
    if (tid < 128) atomicMin(&g_minkey[m0 + tid], mk[tid]);
}

// ==================== refine: exact fp32 rescore of candidates ====================
__global__ void __launch_bounds__(256) refine_kernel(const float* __restrict__ cb) {
    int gw = (blockIdx.x * 256 + threadIdx.x) >> 5;
    int lane = threadIdx.x & 31;
    if (gw >= TOKENS) return;
    const float4* z = (const float4*)(g_z + (size_t)gw * 256);
    float4 z0 = z[lane * 2], z1 = z[lane * 2 + 1];
    int cnt = g_cndcnt[gw];
    if (cnt > CAP) cnt = CAP;
    unsigned long long best = ~0ull;
    int idx0 = (int)(g_minkey[gw] & 0xffffffffu);
    for (int c = -1; c < cnt; c++) {
        int idx = (c < 0) ? idx0 : (int)g_cand[gw * CAP + c];
        const float4* e = (const float4*)(cb + (size_t)idx * 256);
        float4 e0 = e[lane * 2], e1 = e[lane * 2 + 1];
        float d = z0.x * e0.x + z0.y * e0.y + z0.z * e0.z + z0.w * e0.w
                + z1.x * e1.x + z1.y * e1.y + z1.z * e1.z + z1.w * e1.w;
#pragma unroll
        for (int o = 16; o; o >>= 1) d += __shfl_xor_sync(0xffffffffu, d, o);
        float s = fmaf(-2.0f, d, g_e2[idx]);
        unsigned long long key = ((unsigned long long)fkey(s) << 32) | (unsigned int)idx;
        if (key < best) best = key;
    }
    if (lane == 0) g_minkey[gw] = best;
}

// ==================== decoder: out = ehi[idx] @ dwt^T + dec_b ====================
#define DCB_OFF  65536
#define DCI_OFF  98304
#define DC_SMEM  98816

__device__ __forceinline__ void load_b_stage(uint32_t sdst, const __nv_bfloat16* gsrc, int tid) {
#pragma unroll
    for (int i = 0; i < 4; i++) {
        int q = tid + 256 * i;
        int r = q >> 3, c = q & 7;
        uint32_t dst = sdst + r * 128 + ((c ^ (r & 7)) << 4);
        cp_async16(dst, gsrc + (size_t)r * 256 + c * 8);
    }
}

__global__ void __launch_bounds__(256, 2) dec_kernel(const float* __restrict__ bias,
                                                     float* __restrict__ C) {
    extern __shared__ char sm[];
    uint32_t sb = smem_u32(sm);
    int tid = threadIdx.x;
    int lane = tid & 31, wid = tid >> 5;
    int warp_m = wid & 1, warp_n = wid >> 1;
    int m0 = blockIdx.y * 128, n0 = blockIdx.x * 128;

    int* idxs = (int*)(sm + DCI_OFF);
    if (tid < 128) idxs[tid] = (int)(g_minkey[m0 + tid] & 0xffffffffu);
    __syncthreads();

#pragma unroll
    for (int i = 0; i < 16; i++) {
        int q = tid + 256 * i;
        int r = q >> 5, c = q & 31;
        uint32_t dst = sb + r * 512 + (c >> 3) * 128 + (((c & 7) ^ (r & 7)) << 4);
        cp_async16(dst, g_ehi + (size_t)idxs[r] * 256 + c * 8);
    }
    cp_commit();
    load_b_stage(sb + DCB_OFF, g_dwt + (size_t)n0 * 256, tid);
    cp_commit();

    float acc[4][4][4];
#pragma unroll
    for (int i = 0; i < 4; i++)
#pragma unroll
        for (int j = 0; j < 4; j++)
#pragma unroll
            for (int q = 0; q < 4; q++) acc[i][j][q] = 0.0f;

    for (int st = 0; st < 4; st++) {
        if (st < 3) {
            load_b_stage(sb + DCB_OFF + ((st + 1) & 1) * 16384,
                         g_dwt + (size_t)n0 * 256 + (st + 1) * 64, tid);
            cp_commit();
            cp_wait1();
        } else cp_wait0();
        __syncthreads();

        uint32_t bbase = sb + DCB_OFF + (st & 1) * 16384;
#pragma unroll
        for (int kk = 0; kk < 4; kk++) {
            uint32_t b[2][4];
#pragma unroll
            for (int jp = 0; jp < 2; jp++) {
                int n = warp_n * 32 + jp * 16 + (lane & 7) + ((lane >> 4) << 3);
                int ch = kk * 2 + ((lane >> 3) & 1);
                ldsm_x4(b[jp][0], b[jp][1], b[jp][2], b[jp][3],
                        bbase + n * 128 + ((ch ^ (n & 7)) << 4));
            }
#pragma unroll
            for (int i = 0; i < 4; i++) {
                int r = warp_m * 64 + i * 16 + (lane & 15);
                int k = st * 64 + kk * 16 + ((lane >> 4) << 3);
                int c32 = k >> 3;
                uint32_t ad = sb + r * 512 + (c32 >> 3) * 128 + (((c32 & 7) ^ (r & 7)) << 4);
                uint32_t a[4];
                ldsm_x4(a[0], a[1], a[2], a[3], ad);
#pragma unroll
                for (int j = 0; j < 4; j++)
                    mma16816(acc[i][j], a, &b[j >> 1][(j & 1) * 2]);
            }
        }
        __syncthreads();
    }

#pragma unroll
    for (int j = 0; j < 4; j++) {
        int n = n0 + warp_n * 32 + j * 8 + (lane & 3) * 2;
        float b0 = bias[n], b1 = bias[n + 1];
#pragma unroll
        for (int i = 0; i < 4; i++) {
            int row = m0 + warp_m * 64 + i * 16 + (lane >> 2);
            *(float2*)(C + (size_t)row * SRCDIM + n) =
                make_float2(acc[i][j][0] + b0, acc[i][j][1] + b1);
            *(float2*)(C + (size_t)(row + 8) * SRCDIM + n) =
                make_float2(acc[i][j][2] + b0, acc[i][j][3] + b1);
        }
    }
}

// ---------------- loss = 1.25 * mean((z_q - z)^2) ----------------
__global__ void loss_kernel(const float* __restrict__ cb) {
    __shared__ float red[256];
    int tid = threadIdx.x;
    float part = 0.0f;
    const int total = TOKENS * EDIM;
    for (int i = blockIdx.x * blockDim.x + tid; i < total; i += gridDim.x * blockDim.x) {
        int t = i >> 8;
        int id = (int)(g_minkey[t] & 0xffffffffu);
        float d = cb[(size_t)id * EDIM + (i & 255)] - g_z[i];
        part += d * d;
    }
    red[tid] = part;
    __syncthreads();
    for (int s = 128; s; s >>= 1) {
        if (tid < s) red[tid] += red[tid + s];
        __syncthreads();
    }
    if (tid == 0) atomicAdd(&g_losssum, red[0]);
}

__global__ void finalize_kernel(float* __restrict__ out, int n) {
    out[n - 1] = 1.25f * g_losssum / (float)(TOKENS * EDIM);
}

// ---------------- launch ----------------
extern "C" void kernel_launch(void* const* d_in, const int* in_sizes, int n_in,
                              void* d_out, int out_size) {
    const float* x     = (const float*)d_in[0];
    const float* enc_w = (const float*)d_in[1];
    const float* enc_b = (const float*)d_in[2];
    const float* cb    = (const float*)d_in[3];
    const float* dec_w = (const float*)d_in[4];
    const float* dec_b = (const float*)d_in[5];
    float* out = (float*)d_out;

    static bool attr_done = false;
    if (!attr_done) {
        cudaFuncSetAttribute(enc_mma, cudaFuncAttributeMaxDynamicSharedMemorySize, EC_SMEM);
        cudaFuncSetAttribute(score_p1, cudaFuncAttributeMaxDynamicSharedMemorySize, SC_SMEM);
        cudaFuncSetAttribute(dec_kernel, cudaFuncAttributeMaxDynamicSharedMemorySize, DC_SMEM);
        attr_done = true;
    }

    prep_all<<<4096, 256>>>(x, enc_w, cb, dec_w);
    enc_mma<<<dim3(EDIM / 128, TOKENS / 128), 256, EC_SMEM>>>(enc_b);
    score_p1<<<dim3(2, TOKENS / 128), 256, SC_SMEM>>>();
    refine_kernel<<<(TOKENS * 32 + 255) / 256, 256>>>(cb);
    dec_kernel<<<dim3(SRCDIM / 128, TOKENS / 128), 256, DC_SMEM>>>(dec_b, out);
    loss_kernel<<<296, 256>>>(cb);
    finalize_kernel<<<1, 1>>>(out, out_size);
}

// round 6
// speedup vs baseline: 4.5555x; 1.0363x over previous
#include <cuda_runtime.h>
#include <cuda_bf16.h>
#include <cstdint>

#define TOKENS 9216
#define EDIM 256
#define SRCDIM 1024
#define NCODES 16384
#define CAP 128
#define TAU 3e-5f

// ---------------- device scratch ----------------
__device__ float g_z[TOKENS * EDIM];
__device__ __nv_bfloat16 g_zhi[TOKENS * EDIM];
__device__ __nv_bfloat16 g_ehi[NCODES * EDIM];
__device__ __nv_bfloat16 g_xhi[TOKENS * SRCDIM];
__device__ __nv_bfloat16 g_xlo[TOKENS * SRCDIM];
__device__ __nv_bfloat16 g_ewhi[EDIM * SRCDIM];   // enc_w^T hi [n][k]
__device__ __nv_bfloat16 g_ewlo[EDIM * SRCDIM];   // enc_w^T lo
__device__ __nv_bfloat16 g_dwt[SRCDIM * EDIM];    // dec_w^T bf16 [n][k]
__device__ float g_e2[NCODES];
__device__ unsigned long long g_minkey[TOKENS];
__device__ int g_cndcnt[TOKENS];
__device__ unsigned int g_cand[TOKENS * CAP];
__device__ float g_losssum;

// ---------------- portable PTX helpers ----------------
__device__ __forceinline__ uint32_t smem_u32(const void* p) {
    uint32_t a;
    asm("{ .reg .u64 t; cvta.to.shared.u64 t, %1; cvt.u32.u64 %0, t; }" : "=r"(a) : "l"(p));
    return a;
}
__device__ __forceinline__ void cp_async16(uint32_t dst, const void* src) {
    asm volatile("cp.async.cg.shared.global [%0], [%1], 16;" :: "r"(dst), "l"(src) : "memory");
}
__device__ __forceinline__ void cp_commit() { asm volatile("cp.async.commit_group;" ::: "memory"); }
__device__ __forceinline__ void cp_wait0() { asm volatile("cp.async.wait_group 0;" ::: "memory"); }
__device__ __forceinline__ void cp_wait1() { asm volatile("cp.async.wait_group 1;" ::: "memory"); }
__device__ __forceinline__ void cp_wait2() { asm volatile("cp.async.wait_group 2;" ::: "memory"); }

__device__ __forceinline__ void ldsm_x4(uint32_t& r0, uint32_t& r1, uint32_t& r2, uint32_t& r3,
                                        uint32_t addr) {
    asm volatile("ldmatrix.sync.aligned.m8n8.x4.shared.b16 {%0,%1,%2,%3}, [%4];"
                 : "=r"(r0), "=r"(r1), "=r"(r2), "=r"(r3) : "r"(addr));
}
__device__ __forceinline__ void mma16816(float* c, const uint32_t* a, const uint32_t* b) {
    asm volatile("mma.sync.aligned.m16n8k16.row.col.f32.bf16.bf16.f32 "
                 "{%0,%1,%2,%3}, {%4,%5,%6,%7}, {%8,%9}, {%0,%1,%2,%3};"
                 : "+f"(c[0]), "+f"(c[1]), "+f"(c[2]), "+f"(c[3])
                 : "r"(a[0]), "r"(a[1]), "r"(a[2]), "r"(a[3]), "r"(b[0]), "r"(b[1]));
}

__device__ __forceinline__ unsigned int fkey(float f) {
    unsigned int u = __float_as_uint(f);
    return (u & 0x80000000u) ? ~u : (u | 0x80000000u);
}
__device__ __forceinline__ float inv_fkey(unsigned int k) {
    unsigned int u = (k & 0x80000000u) ? (k & 0x7fffffffu) : ~k;
    return __uint_as_float(u);
}

// ==================== prep_cb (stream 2): init + codebook bf16-hi + e2 ====================
// grid 2048 x 256
__global__ void __launch_bounds__(256) prep_cb(const float* __restrict__ cb) {
    int bb = blockIdx.x, tid = threadIdx.x;
    int i = bb * 256 + tid;
    if (i < TOKENS) { g_minkey[i] = ~0ull; g_cndcnt[i] = 0; }
    if (i == 0) g_losssum = 0.0f;
    int warp = bb * 8 + (tid >> 5);     // exactly 16384 warps
    int lane = tid & 31;
    size_t base = (size_t)warp * EDIM;
    float s = 0.0f;
#pragma unroll
    for (int q = 0; q < 8; q++) {
        int k = lane * 8 + q;
        float v = cb[base + k];
        g_ehi[base + k] = __float2bfloat16(v);
        s += v * v;
    }
#pragma unroll
    for (int o = 16; o; o >>= 1) s += __shfl_xor_sync(0xffffffffu, s, o);
    if (lane == 0) g_e2[warp] = s;
}

// ==================== prep_misc (main stream): x split + enc_w^T split + dec_w^T ====================
// grid 2048: [0,256) ewt, [256,512) dwt, [512,2048) x split grid-stride
__global__ void __launch_bounds__(256) prep_misc(const float* __restrict__ x,
                                                 const float* __restrict__ enc_w,
                                                 const float* __restrict__ dec_w) {
    __shared__ float t[32][33];
    int b = blockIdx.x, tid = threadIdx.x;
    int tx = tid & 31, ty = tid >> 5;

    if (b < 256) {
        int n0 = (b & 7) * 32, k0 = (b >> 3) * 32;
#pragma unroll
        for (int r = 0; r < 32; r += 8)
            t[ty + r][tx] = enc_w[(size_t)(k0 + ty + r) * EDIM + n0 + tx];
        __syncthreads();
#pragma unroll
        for (int r = 0; r < 32; r += 8) {
            float v = t[tx][ty + r];
            __nv_bfloat16 h = __float2bfloat16(v);
            size_t o = (size_t)(n0 + ty + r) * SRCDIM + k0 + tx;
            g_ewhi[o] = h;
            g_ewlo[o] = __float2bfloat16(v - __bfloat162float(h));
        }
    } else if (b < 512) {
        int idx = b - 256;
        int n0 = (idx & 31) * 32, k0 = (idx >> 5) * 32;
#pragma unroll
        for (int r = 0; r < 32; r += 8)
            t[ty + r][tx] = dec_w[(size_t)(k0 + ty + r) * SRCDIM + n0 + tx];
        __syncthreads();
#pragma unroll
        for (int r = 0; r < 32; r += 8)
            g_dwt[(size_t)(n0 + ty + r) * EDIM + k0 + tx] = __float2bfloat16(t[tx][ty + r]);
    } else {
        const int total4 = TOKENS * SRCDIM / 4;
        for (int i4 = (b - 512) * 256 + tid; i4 < total4; i4 += 1536 * 256) {
            float4 v = ((const float4*)x)[i4];
            __nv_bfloat16 h0 = __float2bfloat16(v.x), h1 = __float2bfloat16(v.y);
            __nv_bfloat16 h2 = __float2bfloat16(v.z), h3 = __float2bfloat16(v.w);
            __nv_bfloat162* hi = (__nv_bfloat162*)g_xhi;
            __nv_bfloat162* lo = (__nv_bfloat162*)g_xlo;
            hi[i4 * 2]     = __nv_bfloat162(h0, h1);
            hi[i4 * 2 + 1] = __nv_bfloat162(h2, h3);
            lo[i4 * 2]     = __nv_bfloat162(__float2bfloat16(v.x - __bfloat162float(h0)),
                                            __float2bfloat16(v.y - __bfloat162float(h1)));
            lo[i4 * 2 + 1] = __nv_bfloat162(__float2bfloat16(v.z - __bfloat162float(h2)),
                                            __float2bfloat16(v.w - __bfloat162float(h3)));
        }
    }
}

// [128 rows][64 k] tile loader, row 128B, XOR swizzle
__device__ __forceinline__ void load_tile64(uint32_t sdst, const __nv_bfloat16* gsrc,
                                            int rowstride, int tid) {
#pragma unroll
    for (int i = 0; i < 4; i++) {
        int q = tid + 256 * i;
        int r = q >> 3, c = q & 7;
        uint32_t dst = sdst + r * 128 + ((c ^ (r & 7)) << 4);
        cp_async16(dst, gsrc + (size_t)r * rowstride + c * 8);
    }
}

// ==================== encoder: z = x @ enc_w + b, split-bf16 3-term mma ====================
#define EC_SMEM 131072

__global__ void __launch_bounds__(256, 1) enc_mma(const float* __restrict__ bias) {
    extern __shared__ char sm[];
    uint32_t sb = smem_u32(sm);
    int tid = threadIdx.x;
    int lane = tid & 31, wid = tid >> 5;
    int warp_m = wid & 1, warp_n = wid >> 1;
    int m0 = blockIdx.y * 128, n0 = blockIdx.x * 128;

    auto load_stage = [&](int c, int buf) {
        uint32_t base = sb + buf * 65536u;
        load_tile64(base,          g_xhi  + (size_t)m0 * SRCDIM + c * 64, SRCDIM, tid);
        load_tile64(base + 16384u, g_xlo  + (size_t)m0 * SRCDIM + c * 64, SRCDIM, tid);
        load_tile64(base + 32768u, g_ewhi + (size_t)n0 * SRCDIM + c * 64, SRCDIM, tid);
        load_tile64(base + 49152u, g_ewlo + (size_t)n0 * SRCDIM + c * 64, SRCDIM, tid);
    };

    float acc[4][4][4];
#pragma unroll
    for (int i = 0; i < 4; i++)
#pragma unroll
        for (int j = 0; j < 4; j++)
#pragma unroll
            for (int q = 0; q < 4; q++) acc[i][j][q] = 0.0f;

    load_stage(0, 0);
    cp_commit();

    for (int c = 0; c < 16; c++) {
        if (c < 15) { load_stage(c + 1, (c + 1) & 1); cp_commit(); cp_wait1(); }
        else cp_wait0();
        __syncthreads();

        uint32_t base = sb + (c & 1) * 65536u;
        uint32_t Ah = base, Al = base + 16384u, Bh = base + 32768u, Bl = base + 49152u;
#pragma unroll
        for (int kk = 0; kk < 4; kk++) {
            uint32_t bh[2][4], bl[2][4];
#pragma unroll
            for (int jp = 0; jp < 2; jp++) {
                int n = warp_n * 32 + jp * 16 + (lane & 7) + ((lane >> 4) << 3);
                int ch = kk * 2 + ((lane >> 3) & 1);
                uint32_t sw = ((ch ^ (n & 7)) << 4);
                ldsm_x4(bh[jp][0], bh[jp][1], bh[jp][2], bh[jp][3], Bh + n * 128 + sw);
                ldsm_x4(bl[jp][0], bl[jp][1], bl[jp][2], bl[jp][3], Bl + n * 128 + sw);
            }
#pragma unroll
            for (int i = 0; i < 4; i++) {
                int r = warp_m * 64 + i * 16 + (lane & 15);
                int kb = kk * 2 + (lane >> 4);
                uint32_t sw = ((kb ^ (r & 7)) << 4);
                uint32_t ah[4], al[4];
                ldsm_x4(ah[0], ah[1], ah[2], ah[3], Ah + r * 128 + sw);
                ldsm_x4(al[0], al[1], al[2], al[3], Al + r * 128 + sw);
#pragma unroll
                for (int j = 0; j < 4; j++) {
                    mma16816(acc[i][j], ah, &bh[j >> 1][(j & 1) * 2]);
                    mma16816(acc[i][j], al, &bh[j >> 1][(j & 1) * 2]);
                    mma16816(acc[i][j], ah, &bl[j >> 1][(j & 1) * 2]);
                }
            }
        }
        __syncthreads();
    }

#pragma unroll
    for (int j = 0; j < 4; j++) {
        int n = n0 + warp_n * 32 + j * 8 + (lane & 3) * 2;
        float b0 = bias[n], b1 = bias[n + 1];
#pragma unroll
        for (int i = 0; i < 4; i++) {
            int row = m0 + warp_m * 64 + i * 16 + (lane >> 2);
#pragma unroll
            for (int q = 0; q < 2; q++) {
                int rr = row + q * 8;
                float v0 = acc[i][j][q * 2] + b0;
                float v1 = acc[i][j][q * 2 + 1] + b1;
                *(float2*)(g_z + (size_t)rr * EDIM + n) = make_float2(v0, v1);
                *(__nv_bfloat162*)(g_zhi + (size_t)rr * EDIM + n) =
                    __nv_bfloat162(__float2bfloat16(v0), __float2bfloat16(v1));
            }
        }
    }
}

// ==================== score phase 1: CTA 128x256, warp 64x64, 3-stage pipeline ====================
#define SCB_OFF  65536
#define SCE2_OFF 163840
#define SCMK_OFF 164864
#define SC_SMEM  165888
#define NCHUNKS  128          // 32 tiles x 4 k-chunks

__global__ void __launch_bounds__(256, 1) score_p1() {
    extern __shared__ char sm[];
    uint32_t sb = smem_u32(sm);
    int tid = threadIdx.x;
    int lane = tid & 31, wid = tid >> 5;
    int warp_m = wid & 1, warp_n = wid >> 1;
    int m0 = blockIdx.y * 128;
    int nbase = blockIdx.x * 8192;

    unsigned long long* mk = (unsigned long long*)(sm + SCMK_OFF);
    float* e2s = (float*)(sm + SCE2_OFF);
    if (tid < 128) mk[tid] = ~0ull;

    // persistent A (zhi)
    {
        const __nv_bfloat16* zh = g_zhi + (size_t)m0 * 256;
#pragma unroll
        for (int i = 0; i < 16; i++) {
            int q = tid + 256 * i;
            int r = q >> 5, c = q & 31;
            uint32_t dst = sb + r * 512 + (c >> 3) * 128 + (((c & 7) ^ (r & 7)) << 4);
            cp_async16(dst, zh + (size_t)r * 256 + c * 8);
        }
        cp_commit();
    }

    auto load_chunk = [&](int c) {
        uint32_t sdst = sb + SCB_OFF + (uint32_t)(c % 3) * 32768u;
        const __nv_bfloat16* gsrc =
            g_ehi + (size_t)(nbase + (c >> 2) * 256) * 256 + (c & 3) * 64;
#pragma unroll
        for (int i = 0; i < 8; i++) {
            int q = tid + 256 * i;
            int r = q >> 3, cc = q & 7;
            uint32_t dst = sdst + r * 128 + ((cc ^ (r & 7)) << 4);
            cp_async16(dst, gsrc + (size_t)r * 256 + cc * 8);
        }
    };

    load_chunk(0); cp_commit();
    load_chunk(1); cp_commit();

    float acc[4][8][4];
#pragma unroll
    for (int i = 0; i < 4; i++)
#pragma unroll
        for (int j = 0; j < 8; j++)
#pragma unroll
            for (int q = 0; q < 4; q++) acc[i][j][q] = 0.0f;

    for (int c = 0; c < NCHUNKS; c++) {
        if ((c & 3) == 0) e2s[tid] = g_e2[nbase + (c >> 2) * 256 + tid];
        if (c + 2 < NCHUNKS) { load_chunk(c + 2); cp_commit(); }
        int rem = NCHUNKS - 1 - c;
        if (rem >= 2) cp_wait2(); else if (rem == 1) cp_wait1(); else cp_wait0();
        __syncthreads();

        uint32_t bbase = sb + SCB_OFF + (uint32_t)(c % 3) * 32768u;
        int kst = (c & 3) * 64;
#pragma unroll
        for (int kk = 0; kk < 4; kk++) {
            uint32_t bf[4][4];
#pragma unroll
            for (int jp = 0; jp < 4; jp++) {
                int n = warp_n * 64 + jp * 16 + (lane & 7) + ((lane >> 4) << 3);
                int ch = kk * 2 + ((lane >> 3) & 1);
                ldsm_x4(bf[jp][0], bf[jp][1], bf[jp][2], bf[jp][3],
                        bbase + n * 128 + ((ch ^ (n & 7)) << 4));
            }
#pragma unroll
            for (int i = 0; i < 4; i++) {
                int r = warp_m * 64 + i * 16 + (lane & 15);
                int k = kst + kk * 16 + ((lane >> 4) << 3);
                int c32 = k >> 3;
                uint32_t ad = sb + r * 512 + (c32 >> 3) * 128 + (((c32 & 7) ^ (r & 7)) << 4);
                uint32_t a[4];
                ldsm_x4(a[0], a[1], a[2], a[3], ad);
#pragma unroll
                for (int j = 0; j < 8; j++)
                    mma16816(acc[i][j], a, &bf[j >> 1][(j & 1) * 2]);
            }
        }

        if ((c & 3) == 3) {
            int n0 = nbase + (c >> 2) * 256;
            float e2r[16];
#pragma unroll
            for (int j = 0; j < 8; j++) {
                int nl = warp_n * 64 + j * 8 + (lane & 3) * 2;
                e2r[j * 2] = e2s[nl];
                e2r[j * 2 + 1] = e2s[nl + 1];
            }
#pragma unroll
            for (int i = 0; i < 4; i++) {
#pragma unroll
                for (int half = 0; half < 2; half++) {
                    float best = __int_as_float(0x7f800000);
                    int bn = 0;
#pragma unroll
                    for (int j = 0; j < 8; j++) {
#pragma unroll
                        for (int jj = 0; jj < 2; jj++) {
                            float s = fmaf(-2.0f, acc[i][j][half * 2 + jj], e2r[j * 2 + jj]);
                            acc[i][j][half * 2 + jj] = s;
                            int nl = warp_n * 64 + j * 8 + (lane & 3) * 2 + jj;
                            if (s < best) { best = s; bn = nl; }
                        }
                    }
                    unsigned long long key =
                        ((unsigned long long)fkey(best) << 32) | (unsigned int)(n0 + bn);
                    unsigned long long o = __shfl_xor_sync(0xffffffffu, key, 1);
                    if (o < key) key = o;
                    o = __shfl_xor_sync(0xffffffffu, key, 2);
                    if (o < key) key = o;
                    if ((lane & 3) == 0)
                        atomicMin(&mk[warp_m * 64 + i * 16 + (lane >> 2) + half * 8], key);
                }
            }
            __syncthreads();
#pragma unroll
            for (int i = 0; i < 4; i++) {
#pragma unroll
                for (int half = 0; half < 2; half++) {
                    int rowl = warp_m * 64 + i * 16 + (lane >> 2) + half * 8;
                    float thresh = inv_fkey((unsigned int)(mk[rowl] >> 32)) + TAU;
                    int rowg = m0 + rowl;
#pragma unroll
                    for (int j = 0; j < 8; j++) {
#pragma unroll
                        for (int jj = 0; jj < 2; jj++) {
                            float s = acc[i][j][half * 2 + jj];
                            acc[i][j][half * 2 + jj] = 0.0f;
                            if (s < thresh) {
                                int n = n0 + warp_n * 64 + j * 8 + (lane & 3) * 2 + jj;
                                int pos = atomicAdd(&g_cndcnt[rowg], 1);
                                if (pos < CAP) g_cand[rowg * CAP + pos] = (unsigned int)n;
                            }
                        }
                    }
                }
            }
        }
        __syncthreads();
    }
    if (tid < 128) atomicMin(&g_minkey[m0 + tid], mk[tid]);
}

// ==================== refine + loss: exact fp32 rescore, fused loss accumulation ====================
__global__ void __launch_bounds__(256) refine_loss(const float* __restrict__ cb) {
    __shared__ float ls[8];
    int wid = threadIdx.x >> 5;
    int gw = blockIdx.x * 8 + wid;
    int lane = threadIdx.x & 31;
    const float4* z = (const float4*)(g_z + (size_t)gw * 256);
    float4 z0 = z[lane * 2], z1 = z[lane * 2 + 1];
    int cnt = g_cndcnt[gw];
    if (cnt > CAP) cnt = CAP;
    unsigned long long best = ~0ull;
    int idx0 = (int)(g_minkey[gw] & 0xffffffffu);
    for (int c = -1; c < cnt; c++) {
        int idx = (c < 0) ? idx0 : (int)g_cand[gw * CAP + c];
        const float4* e = (const float4*)(cb + (size_t)idx * 256);
        float4 e0 = e[lane * 2], e1 = e[lane * 2 + 1];
        float d = z0.x * e0.x + z0.y * e0.y + z0.z * e0.z + z0.w * e0.w
                + z1.x * e1.x + z1.y * e1.y + z1.z * e1.z + z1.w * e1.w;
#pragma unroll
        for (int o = 16; o; o >>= 1) d += __shfl_xor_sync(0xffffffffu, d, o);
        float s = fmaf(-2.0f, d, g_e2[idx]);
        unsigned long long key = ((unsigned long long)fkey(s) << 32) | (unsigned int)idx;
        if (key < best) best = key;
    }
    int bidx = (int)(best & 0xffffffffu);
    if (lane == 0) g_minkey[gw] = best;
    // loss contribution: sum over dims (cb[bidx] - z)^2
    const float4* e = (const float4*)(cb + (size_t)bidx * 256);
    float4 e0 = e[lane * 2], e1 = e[lane * 2 + 1];
    float dx, l = 0.0f;
    dx = e0.x - z0.x; l += dx * dx;   dx = e0.y - z0.y; l += dx * dx;
    dx = e0.z - z0.z; l += dx * dx;   dx = e0.w - z0.w; l += dx * dx;
    dx = e1.x - z1.x; l += dx * dx;   dx = e1.y - z1.y; l += dx * dx;
    dx = e1.z - z1.z; l += dx * dx;   dx = e1.w - z1.w; l += dx * dx;
#pragma unroll
    for (int o = 16; o; o >>= 1) l += __shfl_xor_sync(0xffffffffu, l, o);
    if (lane == 0) ls[wid] = l;
    __syncthreads();
    if (threadIdx.x == 0) {
        float s = 0.0f;
#pragma unroll
        for (int w = 0; w < 8; w++) s += ls[w];
        atomicAdd(&g_losssum, s);
    }
}

// ==================== decoder: out = ehi[idx] @ dwt^T + dec_b ====================
#define DCB_OFF  65536
#define DCI_OFF  98304
#define DC_SMEM  98816

__device__ __forceinline__ void load_b_stage(uint32_t sdst, const __nv_bfloat16* gsrc, int tid) {
#pragma unroll
    for (int i = 0; i < 4; i++) {
        int q = tid + 256 * i;
        int r = q >> 3, c = q & 7;
        uint32_t dst = sdst + r * 128 + ((c ^ (r & 7)) << 4);
        cp_async16(dst, gsrc + (size_t)r * 256 + c * 8);
    }
}

__global__ void __launch_bounds__(256, 2) dec_kernel(const float* __restrict__ bias,
                                                     float* __restrict__ C) {
    extern __shared__ char sm[];
    uint32_t sb = smem_u32(sm);
    int tid = threadIdx.x;
    int lane = tid & 31, wid = tid >> 5;
    int warp_m = wid & 1, warp_n = wid >> 1;
    int m0 = blockIdx.y * 128, n0 = blockIdx.x * 128;

    int* idxs = (int*)(sm + DCI_OFF);
    if (tid < 128) idxs[tid] = (int)(g_minkey[m0 + tid] & 0xffffffffu);
    __syncthreads();

#pragma unroll
    for (int i = 0; i < 16; i++) {
        int q = tid + 256 * i;
        int r = q >> 5, c = q & 31;
        uint32_t dst = sb + r * 512 + (c >> 3) * 128 + (((c & 7) ^ (r & 7)) << 4);
        cp_async16(dst, g_ehi + (size_t)idxs[r] * 256 + c * 8);
    }
    cp_commit();
    load_b_stage(sb + DCB_OFF, g_dwt + (size_t)n0 * 256, tid);
    cp_commit();

    float acc[4][4][4];
#pragma unroll
    for (int i = 0; i < 4; i++)
#pragma unroll
        for (int j = 0; j < 4; j++)
#pragma unroll
            for (int q = 0; q < 4; q++) acc[i][j][q] = 0.0f;

    for (int st = 0; st < 4; st++) {
        if (st < 3) {
            load_b_stage(sb + DCB_OFF + ((st + 1) & 1) * 16384,
                         g_dwt + (size_t)n0 * 256 + (st + 1) * 64, tid);
            cp_commit();
            cp_wait1();
        } else cp_wait0();
        __syncthreads();

        uint32_t bbase = sb + DCB_OFF + (st & 1) * 16384;
#pragma unroll
        for (int kk = 0; kk < 4; kk++) {
            uint32_t b[2][4];
#pragma unroll
            for (int jp = 0; jp < 2; jp++) {
                int n = warp_n * 32 + jp * 16 + (lane & 7) + ((lane >> 4) << 3);
                int ch = kk * 2 + ((lane >> 3) & 1);
                ldsm_x4(b[jp][0], b[jp][1], b[jp][2], b[jp][3],
                        bbase + n * 128 + ((ch ^ (n & 7)) << 4));
            }
#pragma unroll
            for (int i = 0; i < 4; i++) {
                int r = warp_m * 64 + i * 16 + (lane & 15);
                int k = st * 64 + kk * 16 + ((lane >> 4) << 3);
                int c32 = k >> 3;
                uint32_t ad = sb + r * 512 + (c32 >> 3) * 128 + (((c32 & 7) ^ (r & 7)) << 4);
                uint32_t a[4];
                ldsm_x4(a[0], a[1], a[2], a[3], ad);
#pragma unroll
                for (int j = 0; j < 4; j++)
                    mma16816(acc[i][j], a, &b[j >> 1][(j & 1) * 2]);
            }
        }
        __syncthreads();
    }

#pragma unroll
    for (int j = 0; j < 4; j++) {
        int n = n0 + warp_n * 32 + j * 8 + (lane & 3) * 2;
        float b0 = bias[n], b1 = bias[n + 1];
#pragma unroll
        for (int i = 0; i < 4; i++) {
            int row = m0 + warp_m * 64 + i * 16 + (lane >> 2);
            *(float2*)(C + (size_t)row * SRCDIM + n) =
                make_float2(acc[i][j][0] + b0, acc[i][j][1] + b1);
            *(float2*)(C + (size_t)(row + 8) * SRCDIM + n) =
                make_float2(acc[i][j][2] + b0, acc[i][j][3] + b1);
        }
    }
}

__global__ void finalize_kernel(float* __restrict__ out, int n) {
    out[n - 1] = 1.25f * g_losssum / (float)(TOKENS * EDIM);
}

// ---------------- launch ----------------
extern "C" void kernel_launch(void* const* d_in, const int* in_sizes, int n_in,
                              void* d_out, int out_size) {
    const float* x     = (const float*)d_in[0];
    const float* enc_w = (const float*)d_in[1];
    const float* enc_b = (const float*)d_in[2];
    const float* cb    = (const float*)d_in[3];
    const float* dec_w = (const float*)d_in[4];
    const float* dec_b = (const float*)d_in[5];
    float* out = (float*)d_out;

    static cudaStream_t s2 = nullptr;
    static cudaEvent_t ev0 = nullptr, ev1 = nullptr;
    if (!s2) {
        cudaStreamCreateWithFlags(&s2, cudaStreamNonBlocking);
        cudaEventCreateWithFlags(&ev0, cudaEventDisableTiming);
        cudaEventCreateWithFlags(&ev1, cudaEventDisableTiming);
        cudaFuncSetAttribute(enc_mma, cudaFuncAttributeMaxDynamicSharedMemorySize, EC_SMEM);
        cudaFuncSetAttribute(score_p1, cudaFuncAttributeMaxDynamicSharedMemorySize, SC_SMEM);
        cudaFuncSetAttribute(dec_kernel, cudaFuncAttributeMaxDynamicSharedMemorySize, DC_SMEM);
    }

    // fork: prep_cb on s2, enc chain on main stream
    cudaEventRecord(ev0, 0);
    cudaStreamWaitEvent(s2, ev0, 0);
    prep_cb<<<2048, 256, 0, s2>>>(cb);
    cudaEventRecord(ev1, s2);

    prep_misc<<<2048, 256>>>(x, enc_w, dec_w);
    enc_mma<<<dim3(EDIM / 128, TOKENS / 128), 256, EC_SMEM>>>(enc_b);

    // join: score needs both
    cudaStreamWaitEvent(0, ev1, 0);
    score_p1<<<dim3(2, TOKENS / 128), 256, SC_SMEM>>>();
    refine_loss<<<TOKENS / 8, 256>>>(cb);
    dec_kernel<<<dim3(SRCDIM / 128, TOKENS / 128), 256, DC_SMEM>>>(dec_b, out);
    finalize_kernel<<<1, 1>>>(out, out_size);
}

// round 7
// speedup vs baseline: 5.2278x; 1.1476x over previous
#include <cuda_runtime.h>
#include <cuda_bf16.h>
#include <cstdint>

#define TOKENS 9216
#define EDIM 256
#define SRCDIM 1024
#define NCODES 16384
#define CAP 128
#define TAU 3e-5f

// ---------------- device scratch ----------------
__device__ float g_z[TOKENS * EDIM];
__device__ __nv_bfloat16 g_zhi[TOKENS * EDIM];
__device__ __nv_bfloat16 g_ehi[NCODES * EDIM];
__device__ __nv_bfloat16 g_xhi[TOKENS * SRCDIM];
__device__ __nv_bfloat16 g_xlo[TOKENS * SRCDIM];
__device__ __nv_bfloat16 g_ewhi[EDIM * SRCDIM];   // enc_w^T hi [n][k]
__device__ __nv_bfloat16 g_ewlo[EDIM * SRCDIM];   // enc_w^T lo
__device__ __nv_bfloat16 g_dwt[SRCDIM * EDIM];    // dec_w^T bf16 [n][k]
__device__ float g_e2[NCODES];
__device__ unsigned long long g_minkey[TOKENS];
__device__ int g_cndcnt[TOKENS];
__device__ unsigned int g_cand[TOKENS * CAP];
__device__ float g_losssum;

// ---------------- portable PTX helpers ----------------
__device__ __forceinline__ uint32_t smem_u32(const void* p) {
    uint32_t a;
    asm("{ .reg .u64 t; cvta.to.shared.u64 t, %1; cvt.u32.u64 %0, t; }" : "=r"(a) : "l"(p));
    return a;
}
__device__ __forceinline__ void cp_async16(uint32_t dst, const void* src) {
    asm volatile("cp.async.cg.shared.global [%0], [%1], 16;" :: "r"(dst), "l"(src) : "memory");
}
__device__ __forceinline__ void cp_commit() { asm volatile("cp.async.commit_group;" ::: "memory"); }
__device__ __forceinline__ void cp_wait0() { asm volatile("cp.async.wait_group 0;" ::: "memory"); }
__device__ __forceinline__ void cp_wait1() { asm volatile("cp.async.wait_group 1;" ::: "memory"); }

__device__ __forceinline__ void ldsm_x4(uint32_t& r0, uint32_t& r1, uint32_t& r2, uint32_t& r3,
                                        uint32_t addr) {
    asm volatile("ldmatrix.sync.aligned.m8n8.x4.shared.b16 {%0,%1,%2,%3}, [%4];"
                 : "=r"(r0), "=r"(r1), "=r"(r2), "=r"(r3) : "r"(addr));
}
__device__ __forceinline__ void mma16816(float* c, const uint32_t* a, const uint32_t* b) {
    asm volatile("mma.sync.aligned.m16n8k16.row.col.f32.bf16.bf16.f32 "
                 "{%0,%1,%2,%3}, {%4,%5,%6,%7}, {%8,%9}, {%0,%1,%2,%3};"
                 : "+f"(c[0]), "+f"(c[1]), "+f"(c[2]), "+f"(c[3])
                 : "r"(a[0]), "r"(a[1]), "r"(a[2]), "r"(a[3]), "r"(b[0]), "r"(b[1]));
}

__device__ __forceinline__ unsigned int fkey(float f) {
    unsigned int u = __float_as_uint(f);
    return (u & 0x80000000u) ? ~u : (u | 0x80000000u);
}
__device__ __forceinline__ float inv_fkey(unsigned int k) {
    unsigned int u = (k & 0x80000000u) ? (k & 0x7fffffffu) : ~k;
    return __uint_as_float(u);
}

// ==================== prep_cb (stream 2): init + codebook bf16-hi + e2 ====================
__global__ void __launch_bounds__(256) prep_cb(const float* __restrict__ cb) {
    int bb = blockIdx.x, tid = threadIdx.x;
    int i = bb * 256 + tid;
    if (i < TOKENS) { g_minkey[i] = ~0ull; g_cndcnt[i] = 0; }
    if (i == 0) g_losssum = 0.0f;
    int warp = bb * 8 + (tid >> 5);
    int lane = tid & 31;
    size_t base = (size_t)warp * EDIM;
    float s = 0.0f;
#pragma unroll
    for (int q = 0; q < 8; q++) {
        int k = lane * 8 + q;
        float v = cb[base + k];
        g_ehi[base + k] = __float2bfloat16(v);
        s += v * v;
    }
#pragma unroll
    for (int o = 16; o; o >>= 1) s += __shfl_xor_sync(0xffffffffu, s, o);
    if (lane == 0) g_e2[warp] = s;
}

// ==================== prep_misc: x split + enc_w^T split + dec_w^T ====================
__global__ void __launch_bounds__(256) prep_misc(const float* __restrict__ x,
                                                 const float* __restrict__ enc_w,
                                                 const float* __restrict__ dec_w) {
    __shared__ float t[32][33];
    int b = blockIdx.x, tid = threadIdx.x;
    int tx = tid & 31, ty = tid >> 5;

    if (b < 256) {
        int n0 = (b & 7) * 32, k0 = (b >> 3) * 32;
#pragma unroll
        for (int r = 0; r < 32; r += 8)
            t[ty + r][tx] = enc_w[(size_t)(k0 + ty + r) * EDIM + n0 + tx];
        __syncthreads();
#pragma unroll
        for (int r = 0; r < 32; r += 8) {
            float v = t[tx][ty + r];
            __nv_bfloat16 h = __float2bfloat16(v);
            size_t o = (size_t)(n0 + ty + r) * SRCDIM + k0 + tx;
            g_ewhi[o] = h;
            g_ewlo[o] = __float2bfloat16(v - __bfloat162float(h));
        }
    } else if (b < 512) {
        int idx = b - 256;
        int n0 = (idx & 31) * 32, k0 = (idx >> 5) * 32;
#pragma unroll
        for (int r = 0; r < 32; r += 8)
            t[ty + r][tx] = dec_w[(size_t)(k0 + ty + r) * SRCDIM + n0 + tx];
        __syncthreads();
#pragma unroll
        for (int r = 0; r < 32; r += 8)
            g_dwt[(size_t)(n0 + ty + r) * EDIM + k0 + tx] = __float2bfloat16(t[tx][ty + r]);
    } else {
        const int total4 = TOKENS * SRCDIM / 4;
        for (int i4 = (b - 512) * 256 + tid; i4 < total4; i4 += 1536 * 256) {
            float4 v = ((const float4*)x)[i4];
            __nv_bfloat16 h0 = __float2bfloat16(v.x), h1 = __float2bfloat16(v.y);
            __nv_bfloat16 h2 = __float2bfloat16(v.z), h3 = __float2bfloat16(v.w);
            __nv_bfloat162* hi = (__nv_bfloat162*)g_xhi;
            __nv_bfloat162* lo = (__nv_bfloat162*)g_xlo;
            hi[i4 * 2]     = __nv_bfloat162(h0, h1);
            hi[i4 * 2 + 1] = __nv_bfloat162(h2, h3);
            lo[i4 * 2]     = __nv_bfloat162(__float2bfloat16(v.x - __bfloat162float(h0)),
                                            __float2bfloat16(v.y - __bfloat162float(h1)));
            lo[i4 * 2 + 1] = __nv_bfloat162(__float2bfloat16(v.z - __bfloat162float(h2)),
                                            __float2bfloat16(v.w - __bfloat162float(h3)));
        }
    }
}

// [128 rows][64 k] tile loader, row 128B, XOR swizzle
__device__ __forceinline__ void load_tile64(uint32_t sdst, const __nv_bfloat16* gsrc,
                                            int rowstride, int tid) {
#pragma unroll
    for (int i = 0; i < 4; i++) {
        int q = tid + 256 * i;
        int r = q >> 3, c = q & 7;
        uint32_t dst = sdst + r * 128 + ((c ^ (r & 7)) << 4);
        cp_async16(dst, gsrc + (size_t)r * rowstride + c * 8);
    }
}

// ==================== encoder: z = x @ enc_w + b, split-bf16 3-term mma ====================
#define EC_SMEM 131072

__global__ void __launch_bounds__(256, 1) enc_mma(const float* __restrict__ bias) {
    extern __shared__ char sm[];
    uint32_t sb = smem_u32(sm);
    int tid = threadIdx.x;
    int lane = tid & 31, wid = tid >> 5;
    int warp_m = wid & 1, warp_n = wid >> 1;
    int m0 = blockIdx.y * 128, n0 = blockIdx.x * 128;

    auto load_stage = [&](int c, int buf) {
        uint32_t base = sb + buf * 65536u;
        load_tile64(base,          g_xhi  + (size_t)m0 * SRCDIM + c * 64, SRCDIM, tid);
        load_tile64(base + 16384u, g_xlo  + (size_t)m0 * SRCDIM + c * 64, SRCDIM, tid);
        load_tile64(base + 32768u, g_ewhi + (size_t)n0 * SRCDIM + c * 64, SRCDIM, tid);
        load_tile64(base + 49152u, g_ewlo + (size_t)n0 * SRCDIM + c * 64, SRCDIM, tid);
    };

    float acc[4][4][4];
#pragma unroll
    for (int i = 0; i < 4; i++)
#pragma unroll
        for (int j = 0; j < 4; j++)
#pragma unroll
            for (int q = 0; q < 4; q++) acc[i][j][q] = 0.0f;

    load_stage(0, 0);
    cp_commit();

    for (int c = 0; c < 16; c++) {
        if (c < 15) { load_stage(c + 1, (c + 1) & 1); cp_commit(); cp_wait1(); }
        else cp_wait0();
        __syncthreads();

        uint32_t base = sb + (c & 1) * 65536u;
        uint32_t Ah = base, Al = base + 16384u, Bh = base + 32768u, Bl = base + 49152u;
#pragma unroll
        for (int kk = 0; kk < 4; kk++) {
            uint32_t bh[2][4], bl[2][4];
#pragma unroll
            for (int jp = 0; jp < 2; jp++) {
                int n = warp_n * 32 + jp * 16 + (lane & 7) + ((lane >> 4) << 3);
                int ch = kk * 2 + ((lane >> 3) & 1);
                uint32_t sw = ((ch ^ (n & 7)) << 4);
                ldsm_x4(bh[jp][0], bh[jp][1], bh[jp][2], bh[jp][3], Bh + n * 128 + sw);
                ldsm_x4(bl[jp][0], bl[jp][1], bl[jp][2], bl[jp][3], Bl + n * 128 + sw);
            }
#pragma unroll
            for (int i = 0; i < 4; i++) {
                int r = warp_m * 64 + i * 16 + (lane & 15);
                int kb = kk * 2 + (lane >> 4);
                uint32_t sw = ((kb ^ (r & 7)) << 4);
                uint32_t ah[4], al[4];
                ldsm_x4(ah[0], ah[1], ah[2], ah[3], Ah + r * 128 + sw);
                ldsm_x4(al[0], al[1], al[2], al[3], Al + r * 128 + sw);
#pragma unroll
                for (int j = 0; j < 4; j++) {
                    mma16816(acc[i][j], ah, &bh[j >> 1][(j & 1) * 2]);
                    mma16816(acc[i][j], al, &bh[j >> 1][(j & 1) * 2]);
                    mma16816(acc[i][j], ah, &bl[j >> 1][(j & 1) * 2]);
                }
            }
        }
        __syncthreads();
    }

#pragma unroll
    for (int j = 0; j < 4; j++) {
        int n = n0 + warp_n * 32 + j * 8 + (lane & 3) * 2;
        float b0 = bias[n], b1 = bias[n + 1];
#pragma unroll
        for (int i = 0; i < 4; i++) {
            int row = m0 + warp_m * 64 + i * 16 + (lane >> 2);
#pragma unroll
            for (int q = 0; q < 2; q++) {
                int rr = row + q * 8;
                float v0 = acc[i][j][q * 2] + b0;
                float v1 = acc[i][j][q * 2 + 1] + b1;
                *(float2*)(g_z + (size_t)rr * EDIM + n) = make_float2(v0, v1);
                *(__nv_bfloat162*)(g_zhi + (size_t)rr * EDIM + n) =
                    __nv_bfloat162(__float2bfloat16(v0), __float2bfloat16(v1));
            }
        }
    }
}

// ==================== score phase 1: CTA 128x128, warp 64x32, 2 CTAs/SM ====================
// SMEM: A zhi [0,64K); B 2 x 16KB [64K,96K); e2[128] @96K; mk u64[128] @96.5K
#define SCB_OFF  65536
#define SCE2_OFF 98304
#define SCMK_OFF 98816
#define SC_SMEM  99840
#define NCHUNKS  128          // 32 tiles x 4 k-chunks of [128n x 64k]

__global__ void __launch_bounds__(256, 2) score_p1() {
    extern __shared__ char sm[];
    uint32_t sb = smem_u32(sm);
    int tid = threadIdx.x;
    int lane = tid & 31, wid = tid >> 5;
    int warp_m = wid & 1, warp_n = wid >> 1;
    int m0 = blockIdx.y * 128;
    int nbase = blockIdx.x * 4096;

    unsigned long long* mk = (unsigned long long*)(sm + SCMK_OFF);
    float* e2s = (float*)(sm + SCE2_OFF);
    if (tid < 128) mk[tid] = ~0ull;

    // persistent A (zhi), row 512B, swizzled
    {
        const __nv_bfloat16* zh = g_zhi + (size_t)m0 * 256;
#pragma unroll
        for (int i = 0; i < 16; i++) {
            int q = tid + 256 * i;
            int r = q >> 5, c = q & 31;
            uint32_t dst = sb + r * 512 + (c >> 3) * 128 + (((c & 7) ^ (r & 7)) << 4);
            cp_async16(dst, zh + (size_t)r * 256 + c * 8);
        }
        cp_commit();
    }

    // chunk c: tile c>>2 (128 codes), k-seg c&3, buffer c&1
    auto load_chunk = [&](int c) {
        uint32_t sdst = sb + SCB_OFF + (uint32_t)(c & 1) * 16384u;
        const __nv_bfloat16* gsrc =
            g_ehi + (size_t)(nbase + (c >> 2) * 128) * 256 + (c & 3) * 64;
#pragma unroll
        for (int i = 0; i < 4; i++) {
            int q = tid + 256 * i;
            int r = q >> 3, cc = q & 7;
            uint32_t dst = sdst + r * 128 + ((cc ^ (r & 7)) << 4);
            cp_async16(dst, gsrc + (size_t)r * 256 + cc * 8);
        }
    };

    load_chunk(0); cp_commit();

    float acc[4][4][4];
#pragma unroll
    for (int i = 0; i < 4; i++)
#pragma unroll
        for (int j = 0; j < 4; j++)
#pragma unroll
            for (int q = 0; q < 4; q++) acc[i][j][q] = 0.0f;

    for (int c = 0; c < NCHUNKS; c++) {
        if ((c & 3) == 0 && tid < 128) e2s[tid] = g_e2[nbase + (c >> 2) * 128 + tid];
        if (c + 1 < NCHUNKS) { load_chunk(c + 1); cp_commit(); cp_wait1(); }
        else cp_wait0();
        __syncthreads();

        uint32_t bbase = sb + SCB_OFF + (uint32_t)(c & 1) * 16384u;
        int kst = (c & 3) * 64;
#pragma unroll
        for (int kk = 0; kk < 4; kk++) {
            uint32_t bf[2][4];
#pragma unroll
            for (int jp = 0; jp < 2; jp++) {
                int n = warp_n * 32 + jp * 16 + (lane & 7) + ((lane >> 4) << 3);
                int ch = kk * 2 + ((lane >> 3) & 1);
                ldsm_x4(bf[jp][0], bf[jp][1], bf[jp][2], bf[jp][3],
                        bbase + n * 128 + ((ch ^ (n & 7)) << 4));
            }
#pragma unroll
            for (int i = 0; i < 4; i++) {
                int r = warp_m * 64 + i * 16 + (lane & 15);
                int k = kst + kk * 16 + ((lane >> 4) << 3);
                int c32 = k >> 3;
                uint32_t ad = sb + r * 512 + (c32 >> 3) * 128 + (((c32 & 7) ^ (r & 7)) << 4);
                uint32_t a[4];
                ldsm_x4(a[0], a[1], a[2], a[3], ad);
#pragma unroll
                for (int j = 0; j < 4; j++)
                    mma16816(acc[i][j], a, &bf[j >> 1][(j & 1) * 2]);
            }
        }

        if ((c & 3) == 3) {
            int n0 = nbase + (c >> 2) * 128;
            // pass 1: running min
#pragma unroll
            for (int i = 0; i < 4; i++) {
#pragma unroll
                for (int half = 0; half < 2; half++) {
                    float best = __int_as_float(0x7f800000);
                    int bn = 0;
#pragma unroll
                    for (int j = 0; j < 4; j++) {
#pragma unroll
                        for (int jj = 0; jj < 2; jj++) {
                            int nl = warp_n * 32 + j * 8 + (lane & 3) * 2 + jj;
                            float s = fmaf(-2.0f, acc[i][j][half * 2 + jj], e2s[nl]);
                            acc[i][j][half * 2 + jj] = s;
                            if (s < best) { best = s; bn = nl; }
                        }
                    }
                    unsigned long long key =
                        ((unsigned long long)fkey(best) << 32) | (unsigned int)(n0 + bn);
                    unsigned long long o = __shfl_xor_sync(0xffffffffu, key, 1);
                    if (o < key) key = o;
                    o = __shfl_xor_sync(0xffffffffu, key, 2);
                    if (o < key) key = o;
                    if ((lane & 3) == 0)
                        atomicMin(&mk[warp_m * 64 + i * 16 + (lane >> 2) + half * 8], key);
                }
            }
            __syncthreads();
            // pass 2: candidate collection
#pragma unroll
            for (int i = 0; i < 4; i++) {
#pragma unroll
                for (int half = 0; half < 2; half++) {
                    int rowl = warp_m * 64 + i * 16 + (lane >> 2) + half * 8;
                    float thresh = inv_fkey((unsigned int)(mk[rowl] >> 32)) + TAU;
                    int rowg = m0 + rowl;
#pragma unroll
                    for (int j = 0; j < 4; j++) {
#pragma unroll
                        for (int jj = 0; jj < 2; jj++) {
                            float s = acc[i][j][half * 2 + jj];
                            acc[i][j][half * 2 + jj] = 0.0f;
                            if (s < thresh) {
                                int n = n0 + warp_n * 32 + j * 8 + (lane & 3) * 2 + jj;
                                int pos = atomicAdd(&g_cndcnt[rowg], 1);
                                if (pos < CAP) g_cand[rowg * CAP + pos] = (unsigned int)n;
                            }
                        }
                    }
                }
            }
        }
        __syncthreads();
    }
    if (tid < 128) atomicMin(&g_minkey[m0 + tid], mk[tid]);
}

// ==================== refine + loss: exact fp32 rescore, fused loss ====================
__global__ void __launch_bounds__(256) refine_loss(const float* __restrict__ cb) {
    __shared__ float ls[8];
    int wid = threadIdx.x >> 5;
    int gw = blockIdx.x * 8 + wid;
    int lane = threadIdx.x & 31;
    const float4* z = (const float4*)(g_z + (size_t)gw * 256);
    float4 z0 = z[lane * 2], z1 = z[lane * 2 + 1];
    int cnt = g_cndcnt[gw];
    if (cnt > CAP) cnt = CAP;
    unsigned long long best = ~0ull;
    int idx0 = (int)(g_minkey[gw] & 0xffffffffu);
    for (int c = -1; c < cnt; c++) {
        int idx = (c < 0) ? idx0 : (int)g_cand[gw * CAP + c];
        const float4* e = (const float4*)(cb + (size_t)idx * 256);
        float4 e0 = e[lane * 2], e1 = e[lane * 2 + 1];
        float d = z0.x * e0.x + z0.y * e0.y + z0.z * e0.z + z0.w * e0.w
                + z1.x * e1.x + z1.y * e1.y + z1.z * e1.z + z1.w * e1.w;
#pragma unroll
        for (int o = 16; o; o >>= 1) d += __shfl_xor_sync(0xffffffffu, d, o);
        float s = fmaf(-2.0f, d, g_e2[idx]);
        unsigned long long key = ((unsigned long long)fkey(s) << 32) | (unsigned int)idx;
        if (key < best) best = key;
    }
    int bidx = (int)(best & 0xffffffffu);
    if (lane == 0) g_minkey[gw] = best;
    const float4* e = (const float4*)(cb + (size_t)bidx * 256);
    float4 e0 = e[lane * 2], e1 = e[lane * 2 + 1];
    float dx, l = 0.0f;
    dx = e0.x - z0.x; l += dx * dx;   dx = e0.y - z0.y; l += dx * dx;
    dx = e0.z - z0.z; l += dx * dx;   dx = e0.w - z0.w; l += dx * dx;
    dx = e1.x - z1.x; l += dx * dx;   dx = e1.y - z1.y; l += dx * dx;
    dx = e1.z - z1.z; l += dx * dx;   dx = e1.w - z1.w; l += dx * dx;
#pragma unroll
    for (int o = 16; o; o >>= 1) l += __shfl_xor_sync(0xffffffffu, l, o);
    if (lane == 0) ls[wid] = l;
    __syncthreads();
    if (threadIdx.x == 0) {
        float s = 0.0f;
#pragma unroll
        for (int w = 0; w < 8; w++) s += ls[w];
        atomicAdd(&g_losssum, s);
    }
}

// ==================== decoder: out = ehi[idx] @ dwt^T + dec_b ====================
#define DCB_OFF  65536
#define DCI_OFF  98304
#define DC_SMEM  98816

__device__ __forceinline__ void load_b_stage(uint32_t sdst, const __nv_bfloat16* gsrc, int tid) {
#pragma unroll
    for (int i = 0; i < 4; i++) {
        int q = tid + 256 * i;
        int r = q >> 3, c = q & 7;
        uint32_t dst = sdst + r * 128 + ((c ^ (r & 7)) << 4);
        cp_async16(dst, gsrc + (size_t)r * 256 + c * 8);
    }
}

__global__ void __launch_bounds__(256, 2) dec_kernel(const float* __restrict__ bias,
                                                     float* __restrict__ C) {
    extern __shared__ char sm[];
    uint32_t sb = smem_u32(sm);
    int tid = threadIdx.x;
    int lane = tid & 31, wid = tid >> 5;
    int warp_m = wid & 1, warp_n = wid >> 1;
    int m0 = blockIdx.y * 128, n0 = blockIdx.x * 128;

    int* idxs = (int*)(sm + DCI_OFF);
    if (tid < 128) idxs[tid] = (int)(g_minkey[m0 + tid] & 0xffffffffu);
    __syncthreads();

#pragma unroll
    for (int i = 0; i < 16; i++) {
        int q = tid + 256 * i;
        int r = q >> 5, c = q & 31;
        uint32_t dst = sb + r * 512 + (c >> 3) * 128 + (((c & 7) ^ (r & 7)) << 4);
        cp_async16(dst, g_ehi + (size_t)idxs[r] * 256 + c * 8);
    }
    cp_commit();
    load_b_stage(sb + DCB_OFF, g_dwt + (size_t)n0 * 256, tid);
    cp_commit();

    float acc[4][4][4];
#pragma unroll
    for (int i = 0; i < 4; i++)
#pragma unroll
        for (int j = 0; j < 4; j++)
#pragma unroll
            for (int q = 0; q < 4; q++) acc[i][j][q] = 0.0f;

    for (int st = 0; st < 4; st++) {
        if (st < 3) {
            load_b_stage(sb + DCB_OFF + ((st + 1) & 1) * 16384,
                         g_dwt + (size_t)n0 * 256 + (st + 1) * 64, tid);
            cp_commit();
            cp_wait1();
        } else cp_wait0();
        __syncthreads();

        uint32_t bbase = sb + DCB_OFF + (st & 1) * 16384;
#pragma unroll
        for (int kk = 0; kk < 4; kk++) {
            uint32_t b[2][4];
#pragma unroll
            for (int jp = 0; jp < 2; jp++) {
                int n = warp_n * 32 + jp * 16 + (lane & 7) + ((lane >> 4) << 3);
                int ch = kk * 2 + ((lane >> 3) & 1);
                ldsm_x4(b[jp][0], b[jp][1], b[jp][2], b[jp][3],
                        bbase + n * 128 + ((ch ^ (n & 7)) << 4));
            }
#pragma unroll
            for (int i = 0; i < 4; i++) {
                int r = warp_m * 64 + i * 16 + (lane & 15);
                int k = st * 64 + kk * 16 + ((lane >> 4) << 3);
                int c32 = k >> 3;
                uint32_t ad = sb + r * 512 + (c32 >> 3) * 128 + (((c32 & 7) ^ (r & 7)) << 4);
                uint32_t a[4];
                ldsm_x4(a[0], a[1], a[2], a[3], ad);
#pragma unroll
                for (int j = 0; j < 4; j++)
                    mma16816(acc[i][j], a, &b[j >> 1][(j & 1) * 2]);
            }
        }
        __syncthreads();
    }

#pragma unroll
    for (int j = 0; j < 4; j++) {
        int n = n0 + warp_n * 32 + j * 8 + (lane & 3) * 2;
        float b0 = bias[n], b1 = bias[n + 1];
#pragma unroll
        for (int i = 0; i < 4; i++) {
            int row = m0 + warp_m * 64 + i * 16 + (lane >> 2);
            *(float2*)(C + (size_t)row * SRCDIM + n) =
                make_float2(acc[i][j][0] + b0, acc[i][j][1] + b1);
            *(float2*)(C + (size_t)(row + 8) * SRCDIM + n) =
                make_float2(acc[i][j][2] + b0, acc[i][j][3] + b1);
        }
    }
}

__global__ void finalize_kernel(float* __restrict__ out, int n) {
    out[n - 1] = 1.25f * g_losssum / (float)(TOKENS * EDIM);
}

// ---------------- launch ----------------
extern "C" void kernel_launch(void* const* d_in, const int* in_sizes, int n_in,
                              void* d_out, int out_size) {
    const float* x     = (const float*)d_in[0];
    const float* enc_w = (const float*)d_in[1];
    const float* enc_b = (const float*)d_in[2];
    const float* cb    = (const float*)d_in[3];
    const float* dec_w = (const float*)d_in[4];
    const float* dec_b = (const float*)d_in[5];
    float* out = (float*)d_out;

    static cudaStream_t s2 = nullptr;
    static cudaEvent_t ev0 = nullptr, ev1 = nullptr;
    if (!s2) {
        cudaStreamCreateWithFlags(&s2, cudaStreamNonBlocking);
        cudaEventCreateWithFlags(&ev0, cudaEventDisableTiming);
        cudaEventCreateWithFlags(&ev1, cudaEventDisableTiming);
        cudaFuncSetAttribute(enc_mma, cudaFuncAttributeMaxDynamicSharedMemorySize, EC_SMEM);
        cudaFuncSetAttribute(score_p1, cudaFuncAttributeMaxDynamicSharedMemorySize, SC_SMEM);
        cudaFuncSetAttribute(dec_kernel, cudaFuncAttributeMaxDynamicSharedMemorySize, DC_SMEM);
    }

    cudaEventRecord(ev0, 0);
    cudaStreamWaitEvent(s2, ev0, 0);
    prep_cb<<<2048, 256, 0, s2>>>(cb);
    cudaEventRecord(ev1, s2);

    prep_misc<<<2048, 256>>>(x, enc_w, dec_w);
    enc_mma<<<dim3(EDIM / 128, TOKENS / 128), 256, EC_SMEM>>>(enc_b);

    cudaStreamWaitEvent(0, ev1, 0);
    score_p1<<<dim3(4, TOKENS / 128), 256, SC_SMEM>>>();
    refine_loss<<<TOKENS / 8, 256>>>(cb);
    dec_kernel<<<dim3(SRCDIM / 128, TOKENS / 128), 256, DC_SMEM>>>(dec_b, out);
    finalize_kernel<<<1, 1>>>(out, out_size);
}

// round 8
// speedup vs baseline: 5.3397x; 1.0214x over previous
#include <cuda_runtime.h>
#include <cuda_bf16.h>
#include <cstdint>

#define TOKENS 9216
#define EDIM 256
#define SRCDIM 1024
#define NCODES 16384
#define CAP 128
#define TAU 3e-5f

// ---------------- device scratch ----------------
__device__ float g_z[TOKENS * EDIM];
__device__ __nv_bfloat16 g_zhi[TOKENS * EDIM];
__device__ __nv_bfloat16 g_ehi[NCODES * EDIM];
__device__ __nv_bfloat16 g_xhi[TOKENS * SRCDIM];
__device__ __nv_bfloat16 g_xlo[TOKENS * SRCDIM];
__device__ __nv_bfloat16 g_ewhi[EDIM * SRCDIM];   // enc_w^T hi [n][k]
__device__ __nv_bfloat16 g_ewlo[EDIM * SRCDIM];   // enc_w^T lo
__device__ __nv_bfloat16 g_dwt[SRCDIM * EDIM];    // dec_w^T bf16 [n][k]
__device__ float g_e2[NCODES];
__device__ unsigned long long g_minkey[TOKENS];
__device__ int g_cndcnt[TOKENS];
__device__ unsigned int g_cand[TOKENS * CAP];
__device__ float g_losssum;

// ---------------- portable PTX helpers ----------------
__device__ __forceinline__ uint32_t smem_u32(const void* p) {
    uint32_t a;
    asm("{ .reg .u64 t; cvta.to.shared.u64 t, %1; cvt.u32.u64 %0, t; }" : "=r"(a) : "l"(p));
    return a;
}
__device__ __forceinline__ void cp_async16(uint32_t dst, const void* src) {
    asm volatile("cp.async.cg.shared.global [%0], [%1], 16;" :: "r"(dst), "l"(src) : "memory");
}
__device__ __forceinline__ void cp_commit() { asm volatile("cp.async.commit_group;" ::: "memory"); }
__device__ __forceinline__ void cp_wait0() { asm volatile("cp.async.wait_group 0;" ::: "memory"); }
__device__ __forceinline__ void cp_wait1() { asm volatile("cp.async.wait_group 1;" ::: "memory"); }

__device__ __forceinline__ void ldsm_x4(uint32_t& r0, uint32_t& r1, uint32_t& r2, uint32_t& r3,
                                        uint32_t addr) {
    asm volatile("ldmatrix.sync.aligned.m8n8.x4.shared.b16 {%0,%1,%2,%3}, [%4];"
                 : "=r"(r0), "=r"(r1), "=r"(r2), "=r"(r3) : "r"(addr));
}
__device__ __forceinline__ void mma16816(float* c, const uint32_t* a, const uint32_t* b) {
    asm volatile("mma.sync.aligned.m16n8k16.row.col.f32.bf16.bf16.f32 "
                 "{%0,%1,%2,%3}, {%4,%5,%6,%7}, {%8,%9}, {%0,%1,%2,%3};"
                 : "+f"(c[0]), "+f"(c[1]), "+f"(c[2]), "+f"(c[3])
                 : "r"(a[0]), "r"(a[1]), "r"(a[2]), "r"(a[3]), "r"(b[0]), "r"(b[1]));
}

__device__ __forceinline__ unsigned int fkey(float f) {
    unsigned int u = __float_as_uint(f);
    return (u & 0x80000000u) ? ~u : (u | 0x80000000u);
}
__device__ __forceinline__ float inv_fkey(unsigned int k) {
    unsigned int u = (k & 0x80000000u) ? (k & 0x7fffffffu) : ~k;
    return __uint_as_float(u);
}

// ==================== prep_cb (stream 2): init + codebook bf16-hi + e2 ====================
__global__ void __launch_bounds__(256) prep_cb(const float* __restrict__ cb) {
    int bb = blockIdx.x, tid = threadIdx.x;
    int i = bb * 256 + tid;
    if (i < TOKENS) { g_minkey[i] = ~0ull; g_cndcnt[i] = 0; }
    if (i == 0) g_losssum = 0.0f;
    int warp = bb * 8 + (tid >> 5);
    int lane = tid & 31;
    size_t base = (size_t)warp * EDIM;
    float s = 0.0f;
#pragma unroll
    for (int q = 0; q < 8; q++) {
        int k = lane * 8 + q;
        float v = cb[base + k];
        g_ehi[base + k] = __float2bfloat16(v);
        s += v * v;
    }
#pragma unroll
    for (int o = 16; o; o >>= 1) s += __shfl_xor_sync(0xffffffffu, s, o);
    if (lane == 0) g_e2[warp] = s;
}

// ==================== prep_misc: x split + enc_w^T split + dec_w^T ====================
__global__ void __launch_bounds__(256) prep_misc(const float* __restrict__ x,
                                                 const float* __restrict__ enc_w,
                                                 const float* __restrict__ dec_w) {
    __shared__ float t[32][33];
    int b = blockIdx.x, tid = threadIdx.x;
    int tx = tid & 31, ty = tid >> 5;

    if (b < 256) {
        int n0 = (b & 7) * 32, k0 = (b >> 3) * 32;
#pragma unroll
        for (int r = 0; r < 32; r += 8)
            t[ty + r][tx] = enc_w[(size_t)(k0 + ty + r) * EDIM + n0 + tx];
        __syncthreads();
#pragma unroll
        for (int r = 0; r < 32; r += 8) {
            float v = t[tx][ty + r];
            __nv_bfloat16 h = __float2bfloat16(v);
            size_t o = (size_t)(n0 + ty + r) * SRCDIM + k0 + tx;
            g_ewhi[o] = h;
            g_ewlo[o] = __float2bfloat16(v - __bfloat162float(h));
        }
    } else if (b < 512) {
        int idx = b - 256;
        int n0 = (idx & 31) * 32, k0 = (idx >> 5) * 32;
#pragma unroll
        for (int r = 0; r < 32; r += 8)
            t[ty + r][tx] = dec_w[(size_t)(k0 + ty + r) * SRCDIM + n0 + tx];
        __syncthreads();
#pragma unroll
        for (int r = 0; r < 32; r += 8)
            g_dwt[(size_t)(n0 + ty + r) * EDIM + k0 + tx] = __float2bfloat16(t[tx][ty + r]);
    } else {
        const int total4 = TOKENS * SRCDIM / 4;
        for (int i4 = (b - 512) * 256 + tid; i4 < total4; i4 += 1536 * 256) {
            float4 v = ((const float4*)x)[i4];
            __nv_bfloat16 h0 = __float2bfloat16(v.x), h1 = __float2bfloat16(v.y);
            __nv_bfloat16 h2 = __float2bfloat16(v.z), h3 = __float2bfloat16(v.w);
            __nv_bfloat162* hi = (__nv_bfloat162*)g_xhi;
            __nv_bfloat162* lo = (__nv_bfloat162*)g_xlo;
            hi[i4 * 2]     = __nv_bfloat162(h0, h1);
            hi[i4 * 2 + 1] = __nv_bfloat162(h2, h3);
            lo[i4 * 2]     = __nv_bfloat162(__float2bfloat16(v.x - __bfloat162float(h0)),
                                            __float2bfloat16(v.y - __bfloat162float(h1)));
            lo[i4 * 2 + 1] = __nv_bfloat162(__float2bfloat16(v.z - __bfloat162float(h2)),
                                            __float2bfloat16(v.w - __bfloat162float(h3)));
        }
    }
}

// [128 rows][64 k] tile loader, row 128B, XOR swizzle
__device__ __forceinline__ void load_tile64(uint32_t sdst, const __nv_bfloat16* gsrc,
                                            int rowstride, int tid) {
#pragma unroll
    for (int i = 0; i < 4; i++) {
        int q = tid + 256 * i;
        int r = q >> 3, c = q & 7;
        uint32_t dst = sdst + r * 128 + ((c ^ (r & 7)) << 4);
        cp_async16(dst, gsrc + (size_t)r * rowstride + c * 8);
    }
}

// ==================== encoder: z = x @ enc_w + b, split-bf16 3-term mma ====================
#define EC_SMEM 131072

__global__ void __launch_bounds__(256, 1) enc_mma(const float* __restrict__ bias) {
    extern __shared__ char sm[];
    uint32_t sb = smem_u32(sm);
    int tid = threadIdx.x;
    int lane = tid & 31, wid = tid >> 5;
    int warp_m = wid & 1, warp_n = wid >> 1;
    int m0 = blockIdx.y * 128, n0 = blockIdx.x * 128;

    auto load_stage = [&](int c, int buf) {
        uint32_t base = sb + buf * 65536u;
        load_tile64(base,          g_xhi  + (size_t)m0 * SRCDIM + c * 64, SRCDIM, tid);
        load_tile64(base + 16384u, g_xlo  + (size_t)m0 * SRCDIM + c * 64, SRCDIM, tid);
        load_tile64(base + 32768u, g_ewhi + (size_t)n0 * SRCDIM + c * 64, SRCDIM, tid);
        load_tile64(base + 49152u, g_ewlo + (size_t)n0 * SRCDIM + c * 64, SRCDIM, tid);
    };

    float acc[4][4][4];
#pragma unroll
    for (int i = 0; i < 4; i++)
#pragma unroll
        for (int j = 0; j < 4; j++)
#pragma unroll
            for (int q = 0; q < 4; q++) acc[i][j][q] = 0.0f;

    load_stage(0, 0);
    cp_commit();

    for (int c = 0; c < 16; c++) {
        if (c < 15) { load_stage(c + 1, (c + 1) & 1); cp_commit(); cp_wait1(); }
        else cp_wait0();
        __syncthreads();

        uint32_t base = sb + (c & 1) * 65536u;
        uint32_t Ah = base, Al = base + 16384u, Bh = base + 32768u, Bl = base + 49152u;
#pragma unroll
        for (int kk = 0; kk < 4; kk++) {
            uint32_t bh[2][4], bl[2][4];
#pragma unroll
            for (int jp = 0; jp < 2; jp++) {
                int n = warp_n * 32 + jp * 16 + (lane & 7) + ((lane >> 4) << 3);
                int ch = kk * 2 + ((lane >> 3) & 1);
                uint32_t sw = ((ch ^ (n & 7)) << 4);
                ldsm_x4(bh[jp][0], bh[jp][1], bh[jp][2], bh[jp][3], Bh + n * 128 + sw);
                ldsm_x4(bl[jp][0], bl[jp][1], bl[jp][2], bl[jp][3], Bl + n * 128 + sw);
            }
#pragma unroll
            for (int i = 0; i < 4; i++) {
                int r = warp_m * 64 + i * 16 + (lane & 15);
                int kb = kk * 2 + (lane >> 4);
                uint32_t sw = ((kb ^ (r & 7)) << 4);
                uint32_t ah[4], al[4];
                ldsm_x4(ah[0], ah[1], ah[2], ah[3], Ah + r * 128 + sw);
                ldsm_x4(al[0], al[1], al[2], al[3], Al + r * 128 + sw);
#pragma unroll
                for (int j = 0; j < 4; j++) {
                    mma16816(acc[i][j], ah, &bh[j >> 1][(j & 1) * 2]);
                    mma16816(acc[i][j], al, &bh[j >> 1][(j & 1) * 2]);
                    mma16816(acc[i][j], ah, &bl[j >> 1][(j & 1) * 2]);
                }
            }
        }
        __syncthreads();
    }

#pragma unroll
    for (int j = 0; j < 4; j++) {
        int n = n0 + warp_n * 32 + j * 8 + (lane & 3) * 2;
        float b0 = bias[n], b1 = bias[n + 1];
#pragma unroll
        for (int i = 0; i < 4; i++) {
            int row = m0 + warp_m * 64 + i * 16 + (lane >> 2);
#pragma unroll
            for (int q = 0; q < 2; q++) {
                int rr = row + q * 8;
                float v0 = acc[i][j][q * 2] + b0;
                float v1 = acc[i][j][q * 2 + 1] + b1;
                *(float2*)(g_z + (size_t)rr * EDIM + n) = make_float2(v0, v1);
                *(__nv_bfloat162*)(g_zhi + (size_t)rr * EDIM + n) =
                    __nv_bfloat162(__float2bfloat16(v0), __float2bfloat16(v1));
            }
        }
    }
}

// ==================== score phase 1: CTA 128x128, warp 64x32, 2 CTAs/SM ====================
// A zhi as 4 k-tiles [128x64] @ [0,64K); B 2 x 16KB @ [64K,96K); e2 @96K; mk @96.5K
// All LDSM offsets precomputed per-thread; inner-loop address = tilebase + offset.
#define SCB_OFF  65536
#define SCE2_OFF 98304
#define SCMK_OFF 98816
#define SC_SMEM  99840
#define NCHUNKS  128          // 32 tiles x 4 k-chunks of [128n x 64k]

__global__ void __launch_bounds__(256, 2) score_p1() {
    extern __shared__ char sm[];
    uint32_t sb = smem_u32(sm);
    int tid = threadIdx.x;
    int lane = tid & 31, wid = tid >> 5;
    int warp_m = wid & 1, warp_n = wid >> 1;
    int m0 = blockIdx.y * 128;
    int nbase = blockIdx.x * 4096;

    unsigned long long* mk = (unsigned long long*)(sm + SCMK_OFF);
    float* e2s = (float*)(sm + SCE2_OFF);
    if (tid < 128) mk[tid] = ~0ull;

    // precomputed LDSM offsets (loop-invariant per thread)
    uint32_t aoff[4][4], boff[2][4];
#pragma unroll
    for (int i = 0; i < 4; i++) {
        int r = warp_m * 64 + i * 16 + (lane & 15);
#pragma unroll
        for (int kk = 0; kk < 4; kk++) {
            int ch = kk * 2 + (lane >> 4);
            aoff[i][kk] = (uint32_t)(r * 128 + ((ch ^ (r & 7)) << 4));
        }
    }
#pragma unroll
    for (int jp = 0; jp < 2; jp++) {
        int n = warp_n * 32 + jp * 16 + (lane & 7) + ((lane >> 4) << 3);
#pragma unroll
        for (int kk = 0; kk < 4; kk++) {
            int ch = kk * 2 + ((lane >> 3) & 1);
            boff[jp][kk] = (uint32_t)(n * 128 + ((ch ^ (n & 7)) << 4));
        }
    }

    // persistent A (zhi): 4 k-tiles of [128 rows x 64 k], each row 128B swizzled
    {
        const __nv_bfloat16* zh = g_zhi + (size_t)m0 * 256;
#pragma unroll
        for (int i = 0; i < 16; i++) {
            int q = tid + 256 * i;
            int r = q >> 5, c = q & 31;
            uint32_t dst = sb + (uint32_t)(c >> 3) * 16384u + r * 128 +
                           (((c & 7) ^ (r & 7)) << 4);
            cp_async16(dst, zh + (size_t)r * 256 + c * 8);
        }
        cp_commit();
    }

    // chunk c: tile c>>2 (128 codes), k-seg c&3, buffer c&1
    auto load_chunk = [&](int c) {
        uint32_t sdst = sb + SCB_OFF + (uint32_t)(c & 1) * 16384u;
        const __nv_bfloat16* gsrc =
            g_ehi + (size_t)(nbase + (c >> 2) * 128) * 256 + (c & 3) * 64;
#pragma unroll
        for (int i = 0; i < 4; i++) {
            int q = tid + 256 * i;
            int r = q >> 3, cc = q & 7;
            uint32_t dst = sdst + r * 128 + ((cc ^ (r & 7)) << 4);
            cp_async16(dst, gsrc + (size_t)r * 256 + cc * 8);
        }
    };

    load_chunk(0); cp_commit();

    float acc[4][4][4];
#pragma unroll
    for (int i = 0; i < 4; i++)
#pragma unroll
        for (int j = 0; j < 4; j++)
#pragma unroll
            for (int q = 0; q < 4; q++) acc[i][j][q] = 0.0f;

    for (int c = 0; c < NCHUNKS; c++) {
        if ((c & 3) == 0 && tid < 128) e2s[tid] = g_e2[nbase + (c >> 2) * 128 + tid];
        if (c + 1 < NCHUNKS) { load_chunk(c + 1); cp_commit(); cp_wait1(); }
        else cp_wait0();
        __syncthreads();

        uint32_t abase = sb + (uint32_t)(c & 3) * 16384u;
        uint32_t bbase = sb + SCB_OFF + (uint32_t)(c & 1) * 16384u;
#pragma unroll
        for (int kk = 0; kk < 4; kk++) {
            uint32_t bf[2][4];
            ldsm_x4(bf[0][0], bf[0][1], bf[0][2], bf[0][3], bbase + boff[0][kk]);
            ldsm_x4(bf[1][0], bf[1][1], bf[1][2], bf[1][3], bbase + boff[1][kk]);
#pragma unroll
            for (int i = 0; i < 4; i++) {
                uint32_t a[4];
                ldsm_x4(a[0], a[1], a[2], a[3], abase + aoff[i][kk]);
#pragma unroll
                for (int j = 0; j < 4; j++)
                    mma16816(acc[i][j], a, &bf[j >> 1][(j & 1) * 2]);
            }
        }

        if ((c & 3) == 3) {
            int n0 = nbase + (c >> 2) * 128;
            // pass 1: running min
#pragma unroll
            for (int i = 0; i < 4; i++) {
#pragma unroll
                for (int half = 0; half < 2; half++) {
                    float best = __int_as_float(0x7f800000);
                    int bn = 0;
#pragma unroll
                    for (int j = 0; j < 4; j++) {
#pragma unroll
                        for (int jj = 0; jj < 2; jj++) {
                            int nl = warp_n * 32 + j * 8 + (lane & 3) * 2 + jj;
                            float s = fmaf(-2.0f, acc[i][j][half * 2 + jj], e2s[nl]);
                            acc[i][j][half * 2 + jj] = s;
                            if (s < best) { best = s; bn = nl; }
                        }
                    }
                    unsigned long long key =
                        ((unsigned long long)fkey(best) << 32) | (unsigned int)(n0 + bn);
                    unsigned long long o = __shfl_xor_sync(0xffffffffu, key, 1);
                    if (o < key) key = o;
                    o = __shfl_xor_sync(0xffffffffu, key, 2);
                    if (o < key) key = o;
                    if ((lane & 3) == 0)
                        atomicMin(&mk[warp_m * 64 + i * 16 + (lane >> 2) + half * 8], key);
                }
            }
            __syncthreads();
            // pass 2: candidate collection
#pragma unroll
            for (int i = 0; i < 4; i++) {
#pragma unroll
                for (int half = 0; half < 2; half++) {
                    int rowl = warp_m * 64 + i * 16 + (lane >> 2) + half * 8;
                    float thresh = inv_fkey((unsigned int)(mk[rowl] >> 32)) + TAU;
                    int rowg = m0 + rowl;
#pragma unroll
                    for (int j = 0; j < 4; j++) {
#pragma unroll
                        for (int jj = 0; jj < 2; jj++) {
                            float s = acc[i][j][half * 2 + jj];
                            acc[i][j][half * 2 + jj] = 0.0f;
                            if (s < thresh) {
                                int n = n0 + warp_n * 32 + j * 8 + (lane & 3) * 2 + jj;
                                int pos = atomicAdd(&g_cndcnt[rowg], 1);
                                if (pos < CAP) g_cand[rowg * CAP + pos] = (unsigned int)n;
                            }
                        }
                    }
                }
            }
        }
        __syncthreads();
    }
    if (tid < 128) atomicMin(&g_minkey[m0 + tid], mk[tid]);
}

// ==================== refine + loss: exact fp32 rescore, fused loss ====================
__global__ void __launch_bounds__(256) refine_loss(const float* __restrict__ cb) {
    __shared__ float ls[8];
    int wid = threadIdx.x >> 5;
    int gw = blockIdx.x * 8 + wid;
    int lane = threadIdx.x & 31;
    const float4* z = (const float4*)(g_z + (size_t)gw * 256);
    float4 z0 = z[lane * 2], z1 = z[lane * 2 + 1];
    int cnt = g_cndcnt[gw];
    if (cnt > CAP) cnt = CAP;
    unsigned long long best = ~0ull;
    int idx0 = (int)(g_minkey[gw] & 0xffffffffu);
    for (int c = -1; c < cnt; c++) {
        int idx = (c < 0) ? idx0 : (int)g_cand[gw * CAP + c];
        const float4* e = (const float4*)(cb + (size_t)idx * 256);
        float4 e0 = e[lane * 2], e1 = e[lane * 2 + 1];
        float d = z0.x * e0.x + z0.y * e0.y + z0.z * e0.z + z0.w * e0.w
                + z1.x * e1.x + z1.y * e1.y + z1.z * e1.z + z1.w * e1.w;
#pragma unroll
        for (int o = 16; o; o >>= 1) d += __shfl_xor_sync(0xffffffffu, d, o);
        float s = fmaf(-2.0f, d, g_e2[idx]);
        unsigned long long key = ((unsigned long long)fkey(s) << 32) | (unsigned int)idx;
        if (key < best) best = key;
    }
    int bidx = (int)(best & 0xffffffffu);
    if (lane == 0) g_minkey[gw] = best;
    const float4* e = (const float4*)(cb + (size_t)bidx * 256);
    float4 e0 = e[lane * 2], e1 = e[lane * 2 + 1];
    float dx, l = 0.0f;
    dx = e0.x - z0.x; l += dx * dx;   dx = e0.y - z0.y; l += dx * dx;
    dx = e0.z - z0.z; l += dx * dx;   dx = e0.w - z0.w; l += dx * dx;
    dx = e1.x - z1.x; l += dx * dx;   dx = e1.y - z1.y; l += dx * dx;
    dx = e1.z - z1.z; l += dx * dx;   dx = e1.w - z1.w; l += dx * dx;
#pragma unroll
    for (int o = 16; o; o >>= 1) l += __shfl_xor_sync(0xffffffffu, l, o);
    if (lane == 0) ls[wid] = l;
    __syncthreads();
    if (threadIdx.x == 0) {
        float s = 0.0f;
#pragma unroll
        for (int w = 0; w < 8; w++) s += ls[w];
        atomicAdd(&g_losssum, s);
    }
}

// ==================== decoder: out = ehi[idx] @ dwt^T + dec_b ====================
#define DCB_OFF  65536
#define DCI_OFF  98304
#define DC_SMEM  98816

__device__ __forceinline__ void load_b_stage(uint32_t sdst, const __nv_bfloat16* gsrc, int tid) {
#pragma unroll
    for (int i = 0; i < 4; i++) {
        int q = tid + 256 * i;
        int r = q >> 3, c = q & 7;
        uint32_t dst = sdst + r * 128 + ((c ^ (r & 7)) << 4);
        cp_async16(dst, gsrc + (size_t)r * 256 + c * 8);
    }
}

__global__ void __launch_bounds__(256, 2) dec_kernel(const float* __restrict__ bias,
                                                     float* __restrict__ C) {
    extern __shared__ char sm[];
    uint32_t sb = smem_u32(sm);
    int tid = threadIdx.x;
    int lane = tid & 31, wid = tid >> 5;
    int warp_m = wid & 1, warp_n = wid >> 1;
    int m0 = blockIdx.y * 128, n0 = blockIdx.x * 128;

    int* idxs = (int*)(sm + DCI_OFF);
    if (tid < 128) idxs[tid] = (int)(g_minkey[m0 + tid] & 0xffffffffu);
    __syncthreads();

#pragma unroll
    for (int i = 0; i < 16; i++) {
        int q = tid + 256 * i;
        int r = q >> 5, c = q & 31;
        uint32_t dst = sb + r * 512 + (c >> 3) * 128 + (((c & 7) ^ (r & 7)) << 4);
        cp_async16(dst, g_ehi + (size_t)idxs[r] * 256 + c * 8);
    }
    cp_commit();
    load_b_stage(sb + DCB_OFF, g_dwt + (size_t)n0 * 256, tid);
    cp_commit();

    float acc[4][4][4];
#pragma unroll
    for (int i = 0; i < 4; i++)
#pragma unroll
        for (int j = 0; j < 4; j++)
#pragma unroll
            for (int q = 0; q < 4; q++) acc[i][j][q] = 0.0f;

    for (int st = 0; st < 4; st++) {
        if (st < 3) {
            load_b_stage(sb + DCB_OFF + ((st + 1) & 1) * 16384,
                         g_dwt + (size_t)n0 * 256 + (st + 1) * 64, tid);
            cp_commit();
            cp_wait1();
        } else cp_wait0();
        __syncthreads();

        uint32_t bbase = sb + DCB_OFF + (st & 1) * 16384;
#pragma unroll
        for (int kk = 0; kk < 4; kk++) {
            uint32_t b[2][4];
#pragma unroll
            for (int jp = 0; jp < 2; jp++) {
                int n = warp_n * 32 + jp * 16 + (lane & 7) + ((lane >> 4) << 3);
                int ch = kk * 2 + ((lane >> 3) & 1);
                ldsm_x4(b[jp][0], b[jp][1], b[jp][2], b[jp][3],
                        bbase + n * 128 + ((ch ^ (n & 7)) << 4));
            }
#pragma unroll
            for (int i = 0; i < 4; i++) {
                int r = warp_m * 64 + i * 16 + (lane & 15);
                int k = st * 64 + kk * 16 + ((lane >> 4) << 3);
                int c32 = k >> 3;
                uint32_t ad = sb + r * 512 + (c32 >> 3) * 128 + (((c32 & 7) ^ (r & 7)) << 4);
                uint32_t a[4];
                ldsm_x4(a[0], a[1], a[2], a[3], ad);
#pragma unroll
                for (int j = 0; j < 4; j++)
                    mma16816(acc[i][j], a, &b[j >> 1][(j & 1) * 2]);
            }
        }
        __syncthreads();
    }

#pragma unroll
    for (int j = 0; j < 4; j++) {
        int n = n0 + warp_n * 32 + j * 8 + (lane & 3) * 2;
        float b0 = bias[n], b1 = bias[n + 1];
#pragma unroll
        for (int i = 0; i < 4; i++) {
            int row = m0 + warp_m * 64 + i * 16 + (lane >> 2);
            *(float2*)(C + (size_t)row * SRCDIM + n) =
                make_float2(acc[i][j][0] + b0, acc[i][j][1] + b1);
            *(float2*)(C + (size_t)(row + 8) * SRCDIM + n) =
                make_float2(acc[i][j][2] + b0, acc[i][j][3] + b1);
        }
    }
}

__global__ void finalize_kernel(float* __restrict__ out, int n) {
    out[n - 1] = 1.25f * g_losssum / (float)(TOKENS * EDIM);
}

// ---------------- launch ----------------
extern "C" void kernel_launch(void* const* d_in, const int* in_sizes, int n_in,
                              void* d_out, int out_size) {
    const float* x     = (const float*)d_in[0];
    const float* enc_w = (const float*)d_in[1];
    const float* enc_b = (const float*)d_in[2];
    const float* cb    = (const float*)d_in[3];
    const float* dec_w = (const float*)d_in[4];
    const float* dec_b = (const float*)d_in[5];
    float* out = (float*)d_out;

    static cudaStream_t s2 = nullptr;
    static cudaEvent_t ev0 = nullptr, ev1 = nullptr;
    if (!s2) {
        cudaStreamCreateWithFlags(&s2, cudaStreamNonBlocking);
        cudaEventCreateWithFlags(&ev0, cudaEventDisableTiming);
        cudaEventCreateWithFlags(&ev1, cudaEventDisableTiming);
        cudaFuncSetAttribute(enc_mma, cudaFuncAttributeMaxDynamicSharedMemorySize, EC_SMEM);
        cudaFuncSetAttribute(score_p1, cudaFuncAttributeMaxDynamicSharedMemorySize, SC_SMEM);
        cudaFuncSetAttribute(dec_kernel, cudaFuncAttributeMaxDynamicSharedMemorySize, DC_SMEM);
    }

    cudaEventRecord(ev0, 0);
    cudaStreamWaitEvent(s2, ev0, 0);
    prep_cb<<<2048, 256, 0, s2>>>(cb);
    cudaEventRecord(ev1, s2);

    prep_misc<<<2048, 256>>>(x, enc_w, dec_w);
    enc_mma<<<dim3(EDIM / 128, TOKENS / 128), 256, EC_SMEM>>>(enc_b);

    cudaStreamWaitEvent(0, ev1, 0);
    score_p1<<<dim3(4, TOKENS / 128), 256, SC_SMEM>>>();
    refine_loss<<<TOKENS / 8, 256>>>(cb);
    dec_kernel<<<dim3(SRCDIM / 128, TOKENS / 128), 256, DC_SMEM>>>(dec_b, out);
    finalize_kernel<<<1, 1>>>(out, out_size);
}